// round 14
// baseline (speedup 1.0000x reference)
#include <cuda_runtime.h>
#include <cuda_bf16.h>
#include <cstdint>
#include <math.h>

// Problem constants
static constexpr int Bz   = 32;
static constexpr int INC  = 64;
static constexpr int HIDN = 128;
static constexpr int Gg   = 384;
static constexpr int RR   = 63;
static constexpr int CELLS = RR * RR; // 3969
static constexpr int NCTAS  = 144;    // 4 dirs x 4 kq x 9

// Scratch (allocation-free: __device__ globals)
__device__ float g_gx [(size_t)4 * CELLS * Bz * Gg];    // gx = x@Wx + b   [d][p][q][b][g]
__device__ uint32_t g_hph[(size_t)4 * CELLS * Bz * 64]; // h hi  (bf16x2 k-pair packed) [d][p][q][b][kp]
__device__ uint32_t g_hpm[(size_t)4 * CELLS * Bz * 64]; // h mid residual               [d][p][q][b][kp]
__device__ uint32_t g_Wph[(size_t)4 * 128 * Gg];        // bf16x2 hi of [Wh;Wh2], k-pair packed [d][kp][g]
__device__ uint32_t g_Wpm[(size_t)4 * 128 * Gg];        // bf16x2 mid residual                 [d][kp][g]
__device__ uint32_t g_Wxh[(size_t)4 * 32 * Gg];         // bf16x2 hi of Wx, c-pair packed [d][kp][g]
__device__ uint32_t g_Wxm[(size_t)4 * 32 * Gg];         // bf16x2 mid residual            [d][kp][g]
__device__ uint32_t g_xph[(size_t)4096 * Bz * 32];      // x hi  (bf16x2 c-pair) [i*64+j][b][kp]
__device__ uint32_t g_xpm[(size_t)4096 * Bz * 32];      // x mid residual        [i*64+j][b][kp]
__device__ int g_flag[4 * CELLS];                       // per-cell kq-arrival count (0..4)

// ---------------------------------------------------------------------------
__device__ __forceinline__ unsigned smem_u32(const void* p) {
    return (unsigned)__cvta_generic_to_shared(p);
}
#define CPA16(dst, src) asm volatile("cp.async.cg.shared.global [%0], [%1], 16;" :: "r"(dst), "l"(src))
#define CPC()  asm volatile("cp.async.commit_group;")
#define CPW0() asm volatile("cp.async.wait_group 0;")

#define MMA_BF16(D, a0, a1, a2, a3, bb0, bb1)                                   \
    asm volatile("mma.sync.aligned.m16n8k16.row.col.f32.bf16.bf16.f32 "         \
                 "{%0,%1,%2,%3}, {%4,%5,%6,%7}, {%8,%9}, {%0,%1,%2,%3};"        \
                 : "+f"(D[0]), "+f"(D[1]), "+f"(D[2]), "+f"(D[3])               \
                 : "r"(a0), "r"(a1), "r"(a2), "r"(a3), "r"(bb0), "r"(bb1))

__device__ __forceinline__ float sigf(float x)  { return 1.f / (1.f + __expf(-x)); }
__device__ __forceinline__ float tanhf_fast(float x) {
    float e = __expf(2.f * x);
    return (e - 1.f) / (e + 1.f);
}
__device__ __forceinline__ unsigned pack_bf2(__nv_bfloat16 a, __nv_bfloat16 b) {
    return (unsigned)__bfloat16_as_ushort(a) | ((unsigned)__bfloat16_as_ushort(b) << 16);
}
__device__ __forceinline__ float bf_lo(uint32_t v) {
    return __bfloat162float(__ushort_as_bfloat16((unsigned short)(v & 0xFFFF)));
}
__device__ __forceinline__ float bf_hi(uint32_t v) {
    return __bfloat162float(__ushort_as_bfloat16((unsigned short)(v >> 16)));
}
__device__ __forceinline__ void split2(float a, float b, uint32_t& vh, uint32_t& vm) {
    __nv_bfloat16 ha = __float2bfloat16(a);
    __nv_bfloat16 hb = __float2bfloat16(b);
    vh = pack_bf2(ha, hb);
    vm = pack_bf2(__float2bfloat16(a - __bfloat162float(ha)),
                  __float2bfloat16(b - __bfloat162float(hb)));
}
__device__ __forceinline__ void wait_flag4(const int* f) {
    while (*(volatile const int*)f < 4) { __nanosleep(32); }
}

// ---------------------------------------------------------------------------
// Fill ONLY the uncomputed border cells with 1.0 (one row + one col per dir).
__global__ void __launch_bounds__(256) border_fill_kernel(float* __restrict__ out) {
    const int b = blockIdx.x;
    const int d = blockIdx.y;
    const int row_i = (d & 1) ? 0 : 63;
    const int col_j = (d & 2) ? 0 : 63;
    const int t = threadIdx.x;
    for (int idx = t; idx < 128 * 127; idx += 256) {
        int k = idx / 127;
        int r = idx % 127;
        int i, jj;
        if (r < 64) { i = row_i; jj = r; }
        else {
            int ii = r - 64;                       // 0..62
            i = (ii >= row_i) ? ii + 1 : ii;       // skip row_i
            jj = col_j;
        }
        out[((size_t)(b * 128 + k) * 4 + d) * 4096 + i * 64 + jj] = 1.0f;
    }
}

__global__ void reset_kernel() {
    int i = blockIdx.x * 256 + threadIdx.x;
    if (i < 4 * CELLS) g_flag[i] = 0;
}

// ---------------------------------------------------------------------------
// Split [Wh;Wh2] into bf16 hi/mid, packed by k-pairs: g_Wp*[d][kp][g].
__global__ void wsplit_kernel(const float* __restrict__ Wh,
                              const float* __restrict__ Wh2) {
    int i = blockIdx.x * 256 + threadIdx.x;
    int d  = i / (128 * Gg);
    int kp = (i / Gg) % 128;
    int g  = i % Gg;
    int k0 = 2 * kp, k1 = 2 * kp + 1;
    float w0 = (k0 < 128) ? Wh [((size_t)d * 128 + k0) * Gg + g]
                          : Wh2[((size_t)d * 128 + (k0 - 128)) * Gg + g];
    float w1 = (k1 < 128) ? Wh [((size_t)d * 128 + k1) * Gg + g]
                          : Wh2[((size_t)d * 128 + (k1 - 128)) * Gg + g];
    split2(w0, w1, g_Wph[i], g_Wpm[i]);
}

// Split Wx into bf16 hi/mid, packed by c-pairs: g_Wx*[d][kp][g].
__global__ void wxsplit_kernel(const float* __restrict__ Wx) {
    int i = blockIdx.x * 256 + threadIdx.x;   // 4*32*384 = 49152
    int d  = i / (32 * Gg);
    int kp = (i / Gg) % 32;
    int g  = i % Gg;
    float w0 = Wx[((size_t)d * INC + 2 * kp)     * Gg + g];
    float w1 = Wx[((size_t)d * INC + 2 * kp + 1) * Gg + g];
    split2(w0, w1, g_Wxh[i], g_Wxm[i]);
}

// Transpose+split x: x[b][c][i][j] -> g_xp*[i*64+j][b][kp(c/2)] (bf16x2).
__global__ void __launch_bounds__(256) xsplit_kernel(const float* __restrict__ x) {
    const int ij = blockIdx.x;            // 0..4095
    const int t = threadIdx.x;
#pragma unroll
    for (int f0 = 0; f0 < 1024; f0 += 256) {
        int f = f0 + t;
        int b = f >> 5, kp = f & 31;
        float v0 = x[(((size_t)b * INC + 2 * kp)     << 12) + ij];
        float v1 = x[(((size_t)b * INC + 2 * kp + 1) << 12) + ij];
        uint32_t vh, vm;
        split2(v0, v1, vh, vm);
        size_t off = (size_t)ij * (Bz * 32) + f;
        g_xph[off] = vh;
        g_xpm[off] = vm;
    }
}

// ---------------------------------------------------------------------------
// gx via bf16x3 mma (unchanged from R13 WIN).
static constexpr int GXM_PW = 392;
static constexpr int GXM_PA = 36;
static constexpr int GXM_OFF_WH = 0;
static constexpr int GXM_OFF_WM = GXM_OFF_WH + 32 * GXM_PW;
static constexpr int GXM_OFF_AH = GXM_OFF_WM + 32 * GXM_PW;
static constexpr int GXM_OFF_AM = GXM_OFF_AH + 64 * GXM_PA;
static constexpr int GXM_OFF_BIAS = GXM_OFF_AM + 64 * GXM_PA;
static constexpr int GXM_SMEM = (GXM_OFF_BIAS + Gg) * 4;      // 121856 B

__global__ void __launch_bounds__(256) gx_mma_kernel(const float* __restrict__ bias) {
    extern __shared__ uint32_t smu[];
    uint32_t* Wh_s = smu + GXM_OFF_WH;
    uint32_t* Wm_s = smu + GXM_OFF_WM;
    uint32_t* Ah   = smu + GXM_OFF_AH;
    uint32_t* Am   = smu + GXM_OFF_AM;
    float*    bs   = (float*)(smu + GXM_OFF_BIAS);

    const int pair = blockIdx.x;
    const int p    = blockIdx.y;
    const int d    = blockIdx.z;
    const int q0 = 2 * pair;
    const int q1 = q0 + 1;
    const bool c1ok = (q1 < RR);
    const int t = threadIdx.x;
    const int w = t >> 5, lane = t & 31;
    const int gi = lane >> 2, ci = lane & 3;
    const int mp = w >> 2;
    const int ng = w & 3;

    {
        const int ix = (d & 1) ? (62 - p) : p;
        const int jx0 = (d & 2) ? (62 - q0) : q0;
        const int jx1 = (d & 2) ? (62 - q1) : q1;
        const uint32_t* srcs_h[2] = {
            g_xph + (size_t)(ix * 64 + jx0) * 1024,
            g_xph + (size_t)(ix * 64 + jx1) * 1024 };
        const uint32_t* srcs_m[2] = {
            g_xpm + (size_t)(ix * 64 + jx0) * 1024,
            g_xpm + (size_t)(ix * 64 + jx1) * 1024 };
#pragma unroll
        for (int f0 = 0; f0 < 512; f0 += 256) {
            int f = f0 + t;
            int row = f >> 3;
            int kpc = (f & 7) * 4;
            int cl = row >> 5;
            uint32_t* dh = Ah + row * GXM_PA + kpc;
            uint32_t* dm = Am + row * GXM_PA + kpc;
            if (cl == 0 || c1ok) {
                int srcoff = (row & 31) * 32 + kpc;
                CPA16(smem_u32(dh), srcs_h[cl] + srcoff);
                CPA16(smem_u32(dm), srcs_m[cl] + srcoff);
            } else {
                *(uint4*)dh = make_uint4(0u, 0u, 0u, 0u);
                *(uint4*)dm = make_uint4(0u, 0u, 0u, 0u);
            }
        }
        for (int f = t; f < 32 * 96; f += 256) {
            int kp = f / 96, c16 = (f % 96) * 4;
            size_t gsrc = ((size_t)d * 32 + kp) * Gg + c16;
            CPA16(smem_u32(Wh_s + kp * GXM_PW + c16), g_Wxh + gsrc);
            CPA16(smem_u32(Wm_s + kp * GXM_PW + c16), g_Wxm + gsrc);
        }
        for (int f = t; f < Gg / 4; f += 256) {
            CPA16(smem_u32(bs + f * 4), bias + (size_t)d * Gg + f * 4);
        }
        CPC(); CPW0();
        __syncthreads();
    }

    float acc[2][12][4];
#pragma unroll
    for (int mt = 0; mt < 2; mt++)
#pragma unroll
        for (int nn = 0; nn < 12; nn++)
#pragma unroll
            for (int v = 0; v < 4; v++) acc[mt][nn][v] = 0.f;

    const uint32_t* AhRow = Ah + (mp * 32 + gi) * GXM_PA;
    const uint32_t* AmRow = Am + (mp * 32 + gi) * GXM_PA;

#pragma unroll
    for (int k16 = 0; k16 < 4; k16++) {
        const int kp0 = k16 * 8;
        unsigned ahf[2][4], amf[2][4];
#pragma unroll
        for (int mt = 0; mt < 2; mt++) {
            const uint32_t* Ah0 = AhRow + mt * 16 * GXM_PA + kp0;
            const uint32_t* Am0 = AmRow + mt * 16 * GXM_PA + kp0;
            ahf[mt][0] = Ah0[ci];     ahf[mt][1] = Ah0[8 * GXM_PA + ci];
            ahf[mt][2] = Ah0[ci + 4]; ahf[mt][3] = Ah0[8 * GXM_PA + ci + 4];
            amf[mt][0] = Am0[ci];     amf[mt][1] = Am0[8 * GXM_PA + ci];
            amf[mt][2] = Am0[ci + 4]; amf[mt][3] = Am0[8 * GXM_PA + ci + 4];
        }
#pragma unroll
        for (int nn = 0; nn < 12; nn++) {
            const int c = ng * 96 + nn * 8 + gi;
            unsigned bh0 = Wh_s[(kp0 + ci) * GXM_PW + c];
            unsigned bh1 = Wh_s[(kp0 + ci + 4) * GXM_PW + c];
            unsigned bm0 = Wm_s[(kp0 + ci) * GXM_PW + c];
            unsigned bm1 = Wm_s[(kp0 + ci + 4) * GXM_PW + c];
#pragma unroll
            for (int mt = 0; mt < 2; mt++) {
                MMA_BF16(acc[mt][nn], ahf[mt][0], ahf[mt][1], ahf[mt][2], ahf[mt][3], bh0, bh1);
                MMA_BF16(acc[mt][nn], amf[mt][0], amf[mt][1], amf[mt][2], amf[mt][3], bh0, bh1);
                MMA_BF16(acc[mt][nn], ahf[mt][0], ahf[mt][1], ahf[mt][2], ahf[mt][3], bm0, bm1);
            }
        }
    }

    if (!(mp == 1 && !c1ok)) {
        const size_t cell = (size_t)d * CELLS + (size_t)p * RR + (mp ? q1 : q0);
#pragma unroll
        for (int mt = 0; mt < 2; mt++) {
#pragma unroll
            for (int half = 0; half < 2; half++) {
                const int b = mt * 16 + half * 8 + gi;
                float* gp = g_gx + (cell * Bz + b) * Gg;
#pragma unroll
                for (int nn = 0; nn < 12; nn++) {
                    const int col = ng * 96 + nn * 8 + 2 * ci;
                    float2 v = make_float2(acc[mt][nn][half * 2 + 0] + bs[col],
                                           acc[mt][nn][half * 2 + 1] + bs[col + 1]);
                    *(float2*)(gp + col) = v;
                }
            }
        }
    }
}

// ---------------------------------------------------------------------------
// Persistent bf16x3 wavefront scan with PER-CELL DATAFLOW FLAGS (no grid
// barrier). CTA = (d, kq, j); each completed cell bumps g_flag[cell] (release:
// per-thread threadfence -> syncthreads -> t0 atomicAdd). Consumers spin on
// their 3 parent cells (lf1 == up0) before staging A.
static constexpr int PAD_W = 104;
static constexpr int PAD_A = 132;
static constexpr int OFF_WPH = 0;
static constexpr int OFF_WPM = OFF_WPH + 128 * PAD_W;
static constexpr int OFF_AH  = OFF_WPM + 128 * PAD_W;
static constexpr int OFF_AM  = OFF_AH  + 64 * PAD_A;
static constexpr int SCAN_SMEM = (OFF_AM + 64 * PAD_A) * 4;   // 174080 B

__global__ void __launch_bounds__(256, 1) scan_persist_kernel() {
    extern __shared__ uint32_t smu[];
    uint32_t* Wph_s = smu + OFF_WPH;
    uint32_t* Wpm_s = smu + OFF_WPM;
    uint32_t* Ah    = smu + OFF_AH;
    uint32_t* Am    = smu + OFF_AM;

    const int cta = blockIdx.x;
    const int d  = cta / 36;
    const int kq = (cta / 9) % 4;
    const int j  = cta % 9;
    const int t  = threadIdx.x;
    const int w = t >> 5, lane = t & 31;
    const int gi = lane >> 2, ci = lane & 3;
    const int mp = w >> 2;
    const int ng = w & 3;

    for (int idx = t; idx < 128 * 96; idx += 256) {
        int kp = idx / 96, c = idx % 96;
        int gcol = (c >> 5) * 128 + kq * 32 + (c & 31);
        size_t gsrc = ((size_t)d * 128 + kp) * Gg + gcol;
        Wph_s[kp * PAD_W + c] = g_Wph[gsrc];
        Wpm_s[kp * PAD_W + c] = g_Wpm[gsrc];
    }
    __syncthreads();

    for (int s = 0; s < 2 * RR - 1; s++) {
        const int qlo = (s - (RR - 1) > 0) ? (s - (RR - 1)) : 0;
        const int qhi = (s < RR - 1) ? s : (RR - 1);
        const int npairs = (qhi - qlo + 2) >> 1;

        for (int pi = j; pi < npairs; pi += 9) {
            const int q0 = qlo + 2 * pi;
            const int q1 = q0 + 1;
            const bool c1ok = (q1 <= qhi);
            const int p0 = s - q0;
            const int p1 = s - q1;
            const size_t cell0 = (size_t)d * CELLS + (size_t)p0 * RR + q0;
            const size_t cell1 = (size_t)d * CELLS + (size_t)p1 * RR + q1;

            // ---- wait for parent cells (dataflow sync; lf1 == up0) ----
            if (t == 0  && p0 > 0) wait_flag4(&g_flag[cell0 - RR]);
            if (t == 32 && q0 > 0) wait_flag4(&g_flag[cell0 - 1]);
            if (t == 64 && c1ok && p1 > 0) wait_flag4(&g_flag[cell1 - RR]);
            __syncthreads();
            __threadfence();

            // ---- stage A (pure cp.async copy of pre-split h) ----
            {
#pragma unroll
                for (int f0 = 0; f0 < 2048; f0 += 256) {
                    const int f = f0 + t;
                    const int row = f >> 5;
                    const int c4  = (f & 31) * 4;
                    const int cIdx = row >> 5;
                    const int b = row & 31;
                    const bool isUp = (c4 < 64);
                    const int kloc = isUp ? c4 : (c4 - 64);
                    bool valid;
                    size_t srcCell;
                    if (cIdx == 0) {
                        valid = isUp ? (p0 > 0) : (q0 > 0);
                        srcCell = isUp ? (cell0 - RR) : (cell0 - 1);
                    } else {
                        valid = c1ok && (isUp ? (p1 > 0) : (q1 > 0));
                        srcCell = isUp ? (cell1 - RR) : (cell1 - 1);
                    }
                    uint32_t* dh = Ah + row * PAD_A + c4;
                    uint32_t* dm = Am + row * PAD_A + c4;
                    if (valid) {
                        size_t off = (srcCell * Bz + b) * 64 + kloc;
                        CPA16(smem_u32(dh), g_hph + off);
                        CPA16(smem_u32(dm), g_hpm + off);
                    } else {
                        *(uint4*)dh = make_uint4(0u, 0u, 0u, 0u);
                        *(uint4*)dm = make_uint4(0u, 0u, 0u, 0u);
                    }
                }
                CPC(); CPW0();
                __syncthreads();
            }

            // ---- bf16x3 MMA mainloop over K=256 (16 k16 steps) ----
            float acc[2][3][4];
#pragma unroll
            for (int mt = 0; mt < 2; mt++)
#pragma unroll
                for (int g = 0; g < 3; g++)
#pragma unroll
                    for (int v = 0; v < 4; v++) acc[mt][g][v] = 0.f;

            const int cb0 = ng * 8 + gi;
            const uint32_t* AhRow = Ah + (mp * 32 + gi) * PAD_A;
            const uint32_t* AmRow = Am + (mp * 32 + gi) * PAD_A;

#pragma unroll 2
            for (int k16 = 0; k16 < 16; k16++) {
                const int kp0 = k16 * 8;
                unsigned bh[3][2], bm[3][2];
#pragma unroll
                for (int g = 0; g < 3; g++) {
                    const int c = g * 32 + cb0;
                    bh[g][0] = Wph_s[(kp0 + ci) * PAD_W + c];
                    bh[g][1] = Wph_s[(kp0 + ci + 4) * PAD_W + c];
                    bm[g][0] = Wpm_s[(kp0 + ci) * PAD_W + c];
                    bm[g][1] = Wpm_s[(kp0 + ci + 4) * PAD_W + c];
                }
#pragma unroll
                for (int mt = 0; mt < 2; mt++) {
                    const uint32_t* Ah0 = AhRow + mt * 16 * PAD_A + kp0;
                    const uint32_t* Am0 = AmRow + mt * 16 * PAD_A + kp0;
                    unsigned ah0 = Ah0[ci],           ah1 = Ah0[8 * PAD_A + ci];
                    unsigned ah2 = Ah0[ci + 4],       ah3 = Ah0[8 * PAD_A + ci + 4];
                    unsigned am0 = Am0[ci],           am1 = Am0[8 * PAD_A + ci];
                    unsigned am2 = Am0[ci + 4],       am3 = Am0[8 * PAD_A + ci + 4];
#pragma unroll
                    for (int g = 0; g < 3; g++) {
                        MMA_BF16(acc[mt][g], ah0, ah1, ah2, ah3, bh[g][0], bh[g][1]);
                        MMA_BF16(acc[mt][g], am0, am1, am2, am3, bh[g][0], bh[g][1]);
                        MMA_BF16(acc[mt][g], ah0, ah1, ah2, ah3, bm[g][0], bm[g][1]);
                    }
                }
            }

            // ---- GRU epilogue: warp's cell = mp; store pre-split h ----
            if (!(mp == 1 && !c1ok)) {
                const size_t cell = mp ? cell1 : cell0;
                const int kbase = kq * 32 + ng * 8 + 2 * ci;
                const int kp = kbase >> 1;
#pragma unroll
                for (int mt = 0; mt < 2; mt++) {
#pragma unroll
                    for (int half = 0; half < 2; half++) {
                        const int b = mt * 16 + half * 8 + gi;
                        const int row = mp * 32 + b;
                        const float* gxc = g_gx + (cell * Bz + b) * Gg;
                        float2 gr = __ldcg((const float2*)(gxc + kbase));
                        float2 gz = __ldcg((const float2*)(gxc + 128 + kbase));
                        float2 gn = __ldcg((const float2*)(gxc + 256 + kbase));
                        uint32_t huH = Ah[row * PAD_A + kp];
                        uint32_t huM = Am[row * PAD_A + kp];
                        uint32_t hlH = Ah[row * PAD_A + 64 + kp];
                        uint32_t hlM = Am[row * PAD_A + 64 + kp];
                        float hu0 = bf_lo(huH) + bf_lo(huM);
                        float hu1 = bf_hi(huH) + bf_hi(huM);
                        float hl0 = bf_lo(hlH) + bf_lo(hlM);
                        float hl1 = bf_hi(hlH) + bf_hi(hlM);
                        float r0 = sigf(acc[mt][0][half * 2 + 0] + gr.x);
                        float r1 = sigf(acc[mt][0][half * 2 + 1] + gr.y);
                        float z0 = sigf(acc[mt][1][half * 2 + 0] + gz.x);
                        float z1 = sigf(acc[mt][1][half * 2 + 1] + gz.y);
                        float n0 = tanhf_fast(gn.x + r0 * acc[mt][2][half * 2 + 0]);
                        float n1 = tanhf_fast(gn.y + r1 * acc[mt][2][half * 2 + 1]);
                        float h0 = (1.f - z0) * n0 + z0 * 0.5f * (hu0 + hl0);
                        float h1 = (1.f - z1) * n1 + z1 * 0.5f * (hu1 + hl1);
                        uint32_t vh, vm;
                        split2(h0, h1, vh, vm);
                        size_t off = (cell * Bz + b) * 64 + kp;
                        g_hph[off] = vh;
                        g_hpm[off] = vm;
                    }
                }
            }

            // ---- release: make h visible, then bump cell flags ----
            __threadfence();
            __syncthreads();
            if (t == 0) {
                atomicAdd(&g_flag[cell0], 1);
                if (c1ok) atomicAdd(&g_flag[cell1], 1);
            }
        }
    }
}

// ---------------------------------------------------------------------------
// Post-scan scatter (unchanged from R12 WIN).
__global__ void __launch_bounds__(256) scatter_kernel(float* __restrict__ out) {
    __shared__ float sm[32][129];
    const int bx = blockIdx.x;
    const int b  = blockIdx.y;
    const int d  = blockIdx.z;
    const int p  = bx >> 1;
    const int qt = bx & 1;
    const int qb = qt * 32;
    const int nq = qt ? 31 : 32;
    const int t  = threadIdx.x;

    for (int idx = t; idx < nq * 64; idx += 256) {
        const int qi = idx >> 6;
        const int kp = idx & 63;
        const size_t cell = (size_t)d * CELLS + (size_t)p * RR + (qb + qi);
        const size_t off = (cell * Bz + b) * 64 + kp;
        uint32_t vh = g_hph[off];
        uint32_t vm = g_hpm[off];
        sm[qi][2 * kp]     = bf_lo(vh) + bf_lo(vm);
        sm[qi][2 * kp + 1] = bf_hi(vh) + bf_hi(vm);
    }
    __syncthreads();

    const int oi = (d & 1) ? (63 - p) : p;
    for (int idx = t; idx < 32 * 128; idx += 256) {
        const int k  = idx >> 5;
        const int qi = idx & 31;
        if (qi < nq) {
            const int q  = qb + qi;
            const int oj = (d & 2) ? (63 - q) : q;
            out[((size_t)(b * 128 + k) * 4 + d) * 4096 + (size_t)oi * 64 + oj]
                = sm[qi][k];
        }
    }
}

// ---------------------------------------------------------------------------
extern "C" void kernel_launch(void* const* d_in, const int* in_sizes, int n_in,
                              void* d_out, int out_size) {
    const float* x    = (const float*)d_in[0];
    const float* Wx   = (const float*)d_in[1];
    const float* Wh   = (const float*)d_in[2];
    const float* Wh2  = (const float*)d_in[3];
    const float* bias = (const float*)d_in[4];
    float* out = (float*)d_out;

    cudaFuncSetAttribute(gx_mma_kernel,
                         cudaFuncAttributeMaxDynamicSharedMemorySize, GXM_SMEM);
    cudaFuncSetAttribute(scan_persist_kernel,
                         cudaFuncAttributeMaxDynamicSharedMemorySize, SCAN_SMEM);

    // 1) independent prep
    {
        dim3 grid(32, 4);
        border_fill_kernel<<<grid, 256>>>(out);
    }
    wsplit_kernel<<<768, 256>>>(Wh, Wh2);
    wxsplit_kernel<<<192, 256>>>(Wx);
    xsplit_kernel<<<4096, 256>>>(x);
    reset_kernel<<<(4 * CELLS + 255) / 256, 256>>>();

    // 2) gx via bf16x3 mma
    {
        dim3 grid(32, 63, 4);
        gx_mma_kernel<<<grid, 256, GXM_SMEM>>>(bias);
    }

    // 3) persistent bf16x3 wavefront scan (dataflow-synced, no grid barrier)
    scan_persist_kernel<<<NCTAS, 256, SCAN_SMEM>>>();

    // 4) coalesced transpose of h into the output layout
    {
        dim3 grid(126, 32, 4);
        scatter_kernel<<<grid, 256>>>(out);
    }
}

// round 15
// speedup vs baseline: 1.0643x; 1.0643x over previous
#include <cuda_runtime.h>
#include <cuda_bf16.h>
#include <cstdint>
#include <math.h>

// Problem constants
static constexpr int Bz   = 32;
static constexpr int INC  = 64;
static constexpr int HIDN = 128;
static constexpr int Gg   = 384;
static constexpr int RR   = 63;
static constexpr int CELLS = RR * RR; // 3969
static constexpr int NCTA_D = 36;     // CTAs per direction (4 kq x 9)
static constexpr int NCTAS  = 144;

// Scratch (allocation-free: __device__ globals)
__device__ float g_gx [(size_t)4 * CELLS * Bz * Gg];    // gx = x@Wx + b   [d][p][q][b][g]
__device__ uint32_t g_hph[(size_t)4 * CELLS * Bz * 64]; // h hi  (bf16x2 k-pair packed) [d][p][q][b][kp]
__device__ uint32_t g_hpm[(size_t)4 * CELLS * Bz * 64]; // h mid residual               [d][p][q][b][kp]
__device__ uint32_t g_Wph[(size_t)4 * 128 * Gg];        // bf16x2 hi of [Wh;Wh2], k-pair packed [d][kp][g]
__device__ uint32_t g_Wpm[(size_t)4 * 128 * Gg];        // bf16x2 mid residual                 [d][kp][g]
__device__ uint32_t g_Wxh[(size_t)4 * 32 * Gg];         // bf16x2 hi of Wx, c-pair packed [d][kp][g]
__device__ uint32_t g_Wxm[(size_t)4 * 32 * Gg];         // bf16x2 mid residual            [d][kp][g]
__device__ uint32_t g_xph[(size_t)4096 * Bz * 32];      // x hi  (bf16x2 c-pair) [i*64+j][b][kp]
__device__ uint32_t g_xpm[(size_t)4096 * Bz * 32];      // x mid residual        [i*64+j][b][kp]
__device__ int          g_bar_count[4];
__device__ volatile int g_bar_gen[4];

// ---------------------------------------------------------------------------
__device__ __forceinline__ unsigned smem_u32(const void* p) {
    return (unsigned)__cvta_generic_to_shared(p);
}
#define CPA16(dst, src) asm volatile("cp.async.cg.shared.global [%0], [%1], 16;" :: "r"(dst), "l"(src))
#define CPC()  asm volatile("cp.async.commit_group;")
#define CPW0() asm volatile("cp.async.wait_group 0;")

#define MMA_BF16(D, a0, a1, a2, a3, bb0, bb1)                                   \
    asm volatile("mma.sync.aligned.m16n8k16.row.col.f32.bf16.bf16.f32 "         \
                 "{%0,%1,%2,%3}, {%4,%5,%6,%7}, {%8,%9}, {%0,%1,%2,%3};"        \
                 : "+f"(D[0]), "+f"(D[1]), "+f"(D[2]), "+f"(D[3])               \
                 : "r"(a0), "r"(a1), "r"(a2), "r"(a3), "r"(bb0), "r"(bb1))

__device__ __forceinline__ float sigf(float x)  { return 1.f / (1.f + __expf(-x)); }
__device__ __forceinline__ float tanhf_fast(float x) {
    float e = __expf(2.f * x);
    return (e - 1.f) / (e + 1.f);
}
__device__ __forceinline__ unsigned pack_bf2(__nv_bfloat16 a, __nv_bfloat16 b) {
    return (unsigned)__bfloat16_as_ushort(a) | ((unsigned)__bfloat16_as_ushort(b) << 16);
}
__device__ __forceinline__ float bf_lo(uint32_t v) {
    return __bfloat162float(__ushort_as_bfloat16((unsigned short)(v & 0xFFFF)));
}
__device__ __forceinline__ float bf_hi(uint32_t v) {
    return __bfloat162float(__ushort_as_bfloat16((unsigned short)(v >> 16)));
}
__device__ __forceinline__ void split2(float a, float b, uint32_t& vh, uint32_t& vm) {
    __nv_bfloat16 ha = __float2bfloat16(a);
    __nv_bfloat16 hb = __float2bfloat16(b);
    vh = pack_bf2(ha, hb);
    vm = pack_bf2(__float2bfloat16(a - __bfloat162float(ha)),
                  __float2bfloat16(b - __bfloat162float(hb)));
}

// ---------------------------------------------------------------------------
// Fill ONLY the uncomputed border cells with 1.0 (one row + one col per dir).
__global__ void __launch_bounds__(256) border_fill_kernel(float* __restrict__ out) {
    const int b = blockIdx.x;
    const int d = blockIdx.y;
    const int row_i = (d & 1) ? 0 : 63;
    const int col_j = (d & 2) ? 0 : 63;
    const int t = threadIdx.x;
    for (int idx = t; idx < 128 * 127; idx += 256) {
        int k = idx / 127;
        int r = idx % 127;
        int i, jj;
        if (r < 64) { i = row_i; jj = r; }
        else {
            int ii = r - 64;                       // 0..62
            i = (ii >= row_i) ? ii + 1 : ii;       // skip row_i
            jj = col_j;
        }
        out[((size_t)(b * 128 + k) * 4 + d) * 4096 + i * 64 + jj] = 1.0f;
    }
}

__global__ void reset_kernel() {
    for (int d = 0; d < 4; d++) { g_bar_count[d] = 0; g_bar_gen[d] = 0; }
}

// ---------------------------------------------------------------------------
// Split [Wh;Wh2] into bf16 hi/mid, packed by k-pairs: g_Wp*[d][kp][g].
__global__ void wsplit_kernel(const float* __restrict__ Wh,
                              const float* __restrict__ Wh2) {
    int i = blockIdx.x * 256 + threadIdx.x;
    int d  = i / (128 * Gg);
    int kp = (i / Gg) % 128;
    int g  = i % Gg;
    int k0 = 2 * kp, k1 = 2 * kp + 1;
    float w0 = (k0 < 128) ? Wh [((size_t)d * 128 + k0) * Gg + g]
                          : Wh2[((size_t)d * 128 + (k0 - 128)) * Gg + g];
    float w1 = (k1 < 128) ? Wh [((size_t)d * 128 + k1) * Gg + g]
                          : Wh2[((size_t)d * 128 + (k1 - 128)) * Gg + g];
    split2(w0, w1, g_Wph[i], g_Wpm[i]);
}

// Split Wx into bf16 hi/mid, packed by c-pairs: g_Wx*[d][kp][g].
__global__ void wxsplit_kernel(const float* __restrict__ Wx) {
    int i = blockIdx.x * 256 + threadIdx.x;   // 4*32*384 = 49152
    int d  = i / (32 * Gg);
    int kp = (i / Gg) % 32;
    int g  = i % Gg;
    float w0 = Wx[((size_t)d * INC + 2 * kp)     * Gg + g];
    float w1 = Wx[((size_t)d * INC + 2 * kp + 1) * Gg + g];
    split2(w0, w1, g_Wxh[i], g_Wxm[i]);
}

// Transpose+split x: x[b][c][i][j] -> g_xp*[i*64+j][b][kp(c/2)] (bf16x2).
__global__ void __launch_bounds__(256) xsplit_kernel(const float* __restrict__ x) {
    const int ij = blockIdx.x;            // 0..4095
    const int t = threadIdx.x;
#pragma unroll
    for (int f0 = 0; f0 < 1024; f0 += 256) {
        int f = f0 + t;
        int b = f >> 5, kp = f & 31;
        float v0 = x[(((size_t)b * INC + 2 * kp)     << 12) + ij];
        float v1 = x[(((size_t)b * INC + 2 * kp + 1) << 12) + ij];
        uint32_t vh, vm;
        split2(v0, v1, vh, vm);
        size_t off = (size_t)ij * (Bz * 32) + f;
        g_xph[off] = vh;
        g_xpm[off] = vm;
    }
}

// ---------------------------------------------------------------------------
// gx via bf16x3 mma (unchanged from R13 WIN).
static constexpr int GXM_PW = 392;
static constexpr int GXM_PA = 36;
static constexpr int GXM_OFF_WH = 0;
static constexpr int GXM_OFF_WM = GXM_OFF_WH + 32 * GXM_PW;
static constexpr int GXM_OFF_AH = GXM_OFF_WM + 32 * GXM_PW;
static constexpr int GXM_OFF_AM = GXM_OFF_AH + 64 * GXM_PA;
static constexpr int GXM_OFF_BIAS = GXM_OFF_AM + 64 * GXM_PA;
static constexpr int GXM_SMEM = (GXM_OFF_BIAS + Gg) * 4;      // 121856 B

__global__ void __launch_bounds__(256) gx_mma_kernel(const float* __restrict__ bias) {
    extern __shared__ uint32_t smu[];
    uint32_t* Wh_s = smu + GXM_OFF_WH;
    uint32_t* Wm_s = smu + GXM_OFF_WM;
    uint32_t* Ah   = smu + GXM_OFF_AH;
    uint32_t* Am   = smu + GXM_OFF_AM;
    float*    bs   = (float*)(smu + GXM_OFF_BIAS);

    const int pair = blockIdx.x;
    const int p    = blockIdx.y;
    const int d    = blockIdx.z;
    const int q0 = 2 * pair;
    const int q1 = q0 + 1;
    const bool c1ok = (q1 < RR);
    const int t = threadIdx.x;
    const int w = t >> 5, lane = t & 31;
    const int gi = lane >> 2, ci = lane & 3;
    const int mp = w >> 2;
    const int ng = w & 3;

    {
        const int ix = (d & 1) ? (62 - p) : p;
        const int jx0 = (d & 2) ? (62 - q0) : q0;
        const int jx1 = (d & 2) ? (62 - q1) : q1;
        const uint32_t* srcs_h[2] = {
            g_xph + (size_t)(ix * 64 + jx0) * 1024,
            g_xph + (size_t)(ix * 64 + jx1) * 1024 };
        const uint32_t* srcs_m[2] = {
            g_xpm + (size_t)(ix * 64 + jx0) * 1024,
            g_xpm + (size_t)(ix * 64 + jx1) * 1024 };
#pragma unroll
        for (int f0 = 0; f0 < 512; f0 += 256) {
            int f = f0 + t;
            int row = f >> 3;
            int kpc = (f & 7) * 4;
            int cl = row >> 5;
            uint32_t* dh = Ah + row * GXM_PA + kpc;
            uint32_t* dm = Am + row * GXM_PA + kpc;
            if (cl == 0 || c1ok) {
                int srcoff = (row & 31) * 32 + kpc;
                CPA16(smem_u32(dh), srcs_h[cl] + srcoff);
                CPA16(smem_u32(dm), srcs_m[cl] + srcoff);
            } else {
                *(uint4*)dh = make_uint4(0u, 0u, 0u, 0u);
                *(uint4*)dm = make_uint4(0u, 0u, 0u, 0u);
            }
        }
        for (int f = t; f < 32 * 96; f += 256) {
            int kp = f / 96, c16 = (f % 96) * 4;
            size_t gsrc = ((size_t)d * 32 + kp) * Gg + c16;
            CPA16(smem_u32(Wh_s + kp * GXM_PW + c16), g_Wxh + gsrc);
            CPA16(smem_u32(Wm_s + kp * GXM_PW + c16), g_Wxm + gsrc);
        }
        for (int f = t; f < Gg / 4; f += 256) {
            CPA16(smem_u32(bs + f * 4), bias + (size_t)d * Gg + f * 4);
        }
        CPC(); CPW0();
        __syncthreads();
    }

    float acc[2][12][4];
#pragma unroll
    for (int mt = 0; mt < 2; mt++)
#pragma unroll
        for (int nn = 0; nn < 12; nn++)
#pragma unroll
            for (int v = 0; v < 4; v++) acc[mt][nn][v] = 0.f;

    const uint32_t* AhRow = Ah + (mp * 32 + gi) * GXM_PA;
    const uint32_t* AmRow = Am + (mp * 32 + gi) * GXM_PA;

#pragma unroll
    for (int k16 = 0; k16 < 4; k16++) {
        const int kp0 = k16 * 8;
        unsigned ahf[2][4], amf[2][4];
#pragma unroll
        for (int mt = 0; mt < 2; mt++) {
            const uint32_t* Ah0 = AhRow + mt * 16 * GXM_PA + kp0;
            const uint32_t* Am0 = AmRow + mt * 16 * GXM_PA + kp0;
            ahf[mt][0] = Ah0[ci];     ahf[mt][1] = Ah0[8 * GXM_PA + ci];
            ahf[mt][2] = Ah0[ci + 4]; ahf[mt][3] = Ah0[8 * GXM_PA + ci + 4];
            amf[mt][0] = Am0[ci];     amf[mt][1] = Am0[8 * GXM_PA + ci];
            amf[mt][2] = Am0[ci + 4]; amf[mt][3] = Am0[8 * GXM_PA + ci + 4];
        }
#pragma unroll
        for (int nn = 0; nn < 12; nn++) {
            const int c = ng * 96 + nn * 8 + gi;
            unsigned bh0 = Wh_s[(kp0 + ci) * GXM_PW + c];
            unsigned bh1 = Wh_s[(kp0 + ci + 4) * GXM_PW + c];
            unsigned bm0 = Wm_s[(kp0 + ci) * GXM_PW + c];
            unsigned bm1 = Wm_s[(kp0 + ci + 4) * GXM_PW + c];
#pragma unroll
            for (int mt = 0; mt < 2; mt++) {
                MMA_BF16(acc[mt][nn], ahf[mt][0], ahf[mt][1], ahf[mt][2], ahf[mt][3], bh0, bh1);
                MMA_BF16(acc[mt][nn], amf[mt][0], amf[mt][1], amf[mt][2], amf[mt][3], bh0, bh1);
                MMA_BF16(acc[mt][nn], ahf[mt][0], ahf[mt][1], ahf[mt][2], ahf[mt][3], bm0, bm1);
            }
        }
    }

    if (!(mp == 1 && !c1ok)) {
        const size_t cell = (size_t)d * CELLS + (size_t)p * RR + (mp ? q1 : q0);
#pragma unroll
        for (int mt = 0; mt < 2; mt++) {
#pragma unroll
            for (int half = 0; half < 2; half++) {
                const int b = mt * 16 + half * 8 + gi;
                float* gp = g_gx + (cell * Bz + b) * Gg;
#pragma unroll
                for (int nn = 0; nn < 12; nn++) {
                    const int col = ng * 96 + nn * 8 + 2 * ci;
                    float2 v = make_float2(acc[mt][nn][half * 2 + 0] + bs[col],
                                           acc[mt][nn][half * 2 + 1] + bs[col + 1]);
                    *(float2*)(gp + col) = v;
                }
            }
        }
    }
}

// ---------------------------------------------------------------------------
// Persistent bf16x3 wavefront scan (grid barrier, R13 skeleton) with:
//  - deduped A staging: 3 tiles (up0, lf0, up1) since lf1 == up0 (48KB/task)
//  - double-buffered cross-task A prefetch (staging overlaps mainloop)
// Tile = [32 rows (batch)][64 kp] u32, pad 68; hi & mid arrays.
// K first half (k16 0..7): up tiles x Wh rows; second half: left tiles x Wh2.
static constexpr int PAD_W = 104;    // u32 per W row (96 + 8; 8ci+gi bijective)
static constexpr int PAD_T = 68;     // u32 per tile row (64 + 4; 4gi+ci bijective)
static constexpr int TILE_W = 32 * PAD_T;             // 2176 u32
static constexpr int OFF_WPH = 0;                     // [128][104]
static constexpr int OFF_WPM = OFF_WPH + 128 * PAD_W; // [128][104]
static constexpr int OFF_T   = OFF_WPM + 128 * PAD_W; // [2 buf][2 hm][3 tile][2176]
static constexpr int SCAN_SMEM = (OFF_T + 2 * 2 * 3 * TILE_W) * 4;  // 210944 B

__device__ __forceinline__ void grid_barrier_d(int d, int gen) {
    __syncthreads();
    if (threadIdx.x == 0) {
        __threadfence();
        if (atomicAdd(&g_bar_count[d], 1) == NCTA_D - 1) {
            g_bar_count[d] = 0;
            __threadfence();
            g_bar_gen[d] = gen;
        } else {
            while (g_bar_gen[d] < gen) { __nanosleep(32); }
            __threadfence();
        }
    }
    __syncthreads();
}

__global__ void __launch_bounds__(256, 1) scan_persist_kernel() {
    extern __shared__ uint32_t smu[];
    uint32_t* Wph_s = smu + OFF_WPH;
    uint32_t* Wpm_s = smu + OFF_WPM;

    const int cta = blockIdx.x;
    const int d  = cta / 36;
    const int kq = (cta / 9) % 4;
    const int j  = cta % 9;
    const int t  = threadIdx.x;
    const int w = t >> 5, lane = t & 31;
    const int gi = lane >> 2, ci = lane & 3;
    const int mp = w >> 2;      // cell within pair
    const int ng = w & 3;       // n8 group within each gate's 32 cols
    const size_t dBase = (size_t)d * CELLS;

    // ---- one-time weight staging: col c = gate*32 + koff; kp rows 0..127 ----
    for (int idx = t; idx < 128 * 96; idx += 256) {
        int kp = idx / 96, c = idx % 96;
        int gcol = (c >> 5) * 128 + kq * 32 + (c & 31);
        size_t gsrc = ((size_t)d * 128 + kp) * Gg + gcol;
        Wph_s[kp * PAD_W + c] = g_Wph[gsrc];
        Wpm_s[kp * PAD_W + c] = g_Wpm[gsrc];
    }
    __syncthreads();

    for (int s = 0; s < 2 * RR - 1; s++) {
        const int qlo = (s - (RR - 1) > 0) ? (s - (RR - 1)) : 0;
        const int qhi = (s < RR - 1) ? s : (RR - 1);
        const int npairs = (qhi - qlo + 2) >> 1;

        // stage task pi_'s 3 tiles (up0, lf0, up1) into buffer buf_
        auto stageA = [&](int pi_, int buf_) {
            const int q0_ = qlo + 2 * pi_;
            const int q1_ = q0_ + 1;
            const bool c1_ = (q1_ <= qhi);
            const int p0_ = s - q0_;
            const int p1_ = s - q1_;
            const size_t c0_ = dBase + (size_t)p0_ * RR + q0_;
            const size_t c1_c = dBase + (size_t)p1_ * RR + q1_;
            bool val[3];
            size_t srcC[3];
            val[0] = (p0_ > 0);          srcC[0] = c0_ - RR;   // up0 (== lf1)
            val[1] = (q0_ > 0);          srcC[1] = c0_ - 1;    // lf0
            val[2] = c1_ && (p1_ > 0);   srcC[2] = c1_c - RR;  // up1
            uint32_t* baseH = smu + OFF_T + buf_ * (6 * TILE_W);
#pragma unroll
            for (int f0 = 0; f0 < 1536; f0 += 256) {
                const int f = f0 + t;
                const int tl  = f >> 9;          // tile 0..2
                const int row = (f >> 4) & 31;   // batch row
                const int ch  = f & 15;          // 16B chunk (4 u32)
                uint32_t* dh = baseH + tl * TILE_W + row * PAD_T + ch * 4;
                uint32_t* dm = dh + 3 * TILE_W;
                if (val[tl]) {
                    size_t off = (srcC[tl] * Bz + row) * 64 + ch * 4;
                    CPA16(smem_u32(dh), g_hph + off);
                    CPA16(smem_u32(dm), g_hpm + off);
                } else {
                    *(uint4*)dh = make_uint4(0u, 0u, 0u, 0u);
                    *(uint4*)dm = make_uint4(0u, 0u, 0u, 0u);
                }
            }
        };

        int buf = 0;
        bool havePrefetch = false;

        for (int pi = j; pi < npairs; pi += 9) {
            const int q0 = qlo + 2 * pi;
            const int q1 = q0 + 1;
            const bool c1ok = (q1 <= qhi);
            const int p1 = s - q1;
            const size_t cell0 = dBase + (size_t)(s - q0) * RR + q0;
            const size_t cell1 = dBase + (size_t)p1 * RR + q1;

            if (!havePrefetch) { stageA(pi, buf); CPC(); }
            CPW0();
            __syncthreads();

            // prefetch next task on this diagonal into the other buffer
            const bool nxt = (pi + 9 < npairs);
            if (nxt) { stageA(pi + 9, buf ^ 1); CPC(); }

            uint32_t* bufBase = smu + OFF_T + buf * (6 * TILE_W);

            // ---- bf16x3 MMA mainloop over K=256 (2 halves x 8 k16) ----
            float acc[2][3][4];
#pragma unroll
            for (int mt = 0; mt < 2; mt++)
#pragma unroll
                for (int g = 0; g < 3; g++)
#pragma unroll
                    for (int v = 0; v < 4; v++) acc[mt][g][v] = 0.f;

            const int cb0 = ng * 8 + gi;
            // warp tile selection: half0 = up (cell0->T0, cell1->T2);
            //                      half1 = left (cell0->T1, cell1->T0)
            const uint32_t* AhT[2] = {
                bufBase + (mp ? 2 : 0) * TILE_W,
                bufBase + (mp ? 0 : 1) * TILE_W };

#pragma unroll
            for (int half = 0; half < 2; half++) {
                const uint32_t* Aht = AhT[half];
                const uint32_t* Amt = Aht + 3 * TILE_W;
#pragma unroll 4
                for (int k8 = 0; k8 < 8; k8++) {
                    const int kpl = k8 * 8;              // kp within tile
                    const int kpw = half * 64 + kpl;     // W row
                    unsigned bh[3][2], bm[3][2];
#pragma unroll
                    for (int g = 0; g < 3; g++) {
                        const int c = g * 32 + cb0;
                        bh[g][0] = Wph_s[(kpw + ci) * PAD_W + c];
                        bh[g][1] = Wph_s[(kpw + ci + 4) * PAD_W + c];
                        bm[g][0] = Wpm_s[(kpw + ci) * PAD_W + c];
                        bm[g][1] = Wpm_s[(kpw + ci + 4) * PAD_W + c];
                    }
#pragma unroll
                    for (int mt = 0; mt < 2; mt++) {
                        const uint32_t* Ah0 = Aht + (mt * 16 + gi) * PAD_T + kpl;
                        const uint32_t* Am0 = Amt + (mt * 16 + gi) * PAD_T + kpl;
                        unsigned ah0 = Ah0[ci],     ah1 = Ah0[8 * PAD_T + ci];
                        unsigned ah2 = Ah0[ci + 4], ah3 = Ah0[8 * PAD_T + ci + 4];
                        unsigned am0 = Am0[ci],     am1 = Am0[8 * PAD_T + ci];
                        unsigned am2 = Am0[ci + 4], am3 = Am0[8 * PAD_T + ci + 4];
#pragma unroll
                        for (int g = 0; g < 3; g++) {
                            MMA_BF16(acc[mt][g], ah0, ah1, ah2, ah3, bh[g][0], bh[g][1]);
                            MMA_BF16(acc[mt][g], am0, am1, am2, am3, bh[g][0], bh[g][1]);
                            MMA_BF16(acc[mt][g], ah0, ah1, ah2, ah3, bm[g][0], bm[g][1]);
                        }
                    }
                }
            }

            // ---- GRU epilogue: warp's cell = mp; store pre-split h ----
            if (!(mp == 1 && !c1ok)) {
                const size_t cell = mp ? cell1 : cell0;
                const uint32_t* huT = bufBase + (mp ? 2 : 0) * TILE_W;  // up
                const uint32_t* hlT = bufBase + (mp ? 0 : 1) * TILE_W;  // left
                const uint32_t* huTm = huT + 3 * TILE_W;
                const uint32_t* hlTm = hlT + 3 * TILE_W;
                const int kbase = kq * 32 + ng * 8 + 2 * ci;
                const int kp = kbase >> 1;
#pragma unroll
                for (int mt = 0; mt < 2; mt++) {
#pragma unroll
                    for (int half = 0; half < 2; half++) {
                        const int b = mt * 16 + half * 8 + gi;
                        const float* gxc = g_gx + (cell * Bz + b) * Gg;
                        float2 gr = __ldcg((const float2*)(gxc + kbase));
                        float2 gz = __ldcg((const float2*)(gxc + 128 + kbase));
                        float2 gn = __ldcg((const float2*)(gxc + 256 + kbase));
                        uint32_t huH = huT [b * PAD_T + kp];
                        uint32_t huM = huTm[b * PAD_T + kp];
                        uint32_t hlH = hlT [b * PAD_T + kp];
                        uint32_t hlM = hlTm[b * PAD_T + kp];
                        float hu0 = bf_lo(huH) + bf_lo(huM);
                        float hu1 = bf_hi(huH) + bf_hi(huM);
                        float hl0 = bf_lo(hlH) + bf_lo(hlM);
                        float hl1 = bf_hi(hlH) + bf_hi(hlM);
                        float r0 = sigf(acc[mt][0][half * 2 + 0] + gr.x);
                        float r1 = sigf(acc[mt][0][half * 2 + 1] + gr.y);
                        float z0 = sigf(acc[mt][1][half * 2 + 0] + gz.x);
                        float z1 = sigf(acc[mt][1][half * 2 + 1] + gz.y);
                        float n0 = tanhf_fast(gn.x + r0 * acc[mt][2][half * 2 + 0]);
                        float n1 = tanhf_fast(gn.y + r1 * acc[mt][2][half * 2 + 1]);
                        float h0 = (1.f - z0) * n0 + z0 * 0.5f * (hu0 + hl0);
                        float h1 = (1.f - z1) * n1 + z1 * 0.5f * (hu1 + hl1);
                        uint32_t vh, vm;
                        split2(h0, h1, vh, vm);
                        size_t off = (cell * Bz + b) * 64 + kp;
                        g_hph[off] = vh;
                        g_hpm[off] = vm;
                    }
                }
            }
            __syncthreads();   // epilogue reads done before buffer reuse
            buf ^= 1;
            havePrefetch = nxt;
        }

        grid_barrier_d(d, s + 1);
    }
}

// ---------------------------------------------------------------------------
// Post-scan scatter (unchanged from R12 WIN).
__global__ void __launch_bounds__(256) scatter_kernel(float* __restrict__ out) {
    __shared__ float sm[32][129];
    const int bx = blockIdx.x;
    const int b  = blockIdx.y;
    const int d  = blockIdx.z;
    const int p  = bx >> 1;
    const int qt = bx & 1;
    const int qb = qt * 32;
    const int nq = qt ? 31 : 32;
    const int t  = threadIdx.x;

    for (int idx = t; idx < nq * 64; idx += 256) {
        const int qi = idx >> 6;
        const int kp = idx & 63;
        const size_t cell = (size_t)d * CELLS + (size_t)p * RR + (qb + qi);
        const size_t off = (cell * Bz + b) * 64 + kp;
        uint32_t vh = g_hph[off];
        uint32_t vm = g_hpm[off];
        sm[qi][2 * kp]     = bf_lo(vh) + bf_lo(vm);
        sm[qi][2 * kp + 1] = bf_hi(vh) + bf_hi(vm);
    }
    __syncthreads();

    const int oi = (d & 1) ? (63 - p) : p;
    for (int idx = t; idx < 32 * 128; idx += 256) {
        const int k  = idx >> 5;
        const int qi = idx & 31;
        if (qi < nq) {
            const int q  = qb + qi;
            const int oj = (d & 2) ? (63 - q) : q;
            out[((size_t)(b * 128 + k) * 4 + d) * 4096 + (size_t)oi * 64 + oj]
                = sm[qi][k];
        }
    }
}

// ---------------------------------------------------------------------------
extern "C" void kernel_launch(void* const* d_in, const int* in_sizes, int n_in,
                              void* d_out, int out_size) {
    const float* x    = (const float*)d_in[0];
    const float* Wx   = (const float*)d_in[1];
    const float* Wh   = (const float*)d_in[2];
    const float* Wh2  = (const float*)d_in[3];
    const float* bias = (const float*)d_in[4];
    float* out = (float*)d_out;

    cudaFuncSetAttribute(gx_mma_kernel,
                         cudaFuncAttributeMaxDynamicSharedMemorySize, GXM_SMEM);
    cudaFuncSetAttribute(scan_persist_kernel,
                         cudaFuncAttributeMaxDynamicSharedMemorySize, SCAN_SMEM);

    // 1) independent prep
    {
        dim3 grid(32, 4);
        border_fill_kernel<<<grid, 256>>>(out);
    }
    wsplit_kernel<<<768, 256>>>(Wh, Wh2);
    wxsplit_kernel<<<192, 256>>>(Wx);
    xsplit_kernel<<<4096, 256>>>(x);
    reset_kernel<<<1, 1>>>();

    // 2) gx via bf16x3 mma
    {
        dim3 grid(32, 63, 4);
        gx_mma_kernel<<<grid, 256, GXM_SMEM>>>(bias);
    }

    // 3) persistent bf16x3 wavefront scan (grid barrier + prefetch)
    scan_persist_kernel<<<NCTAS, 256, SCAN_SMEM>>>();

    // 4) coalesced transpose of h into the output layout
    {
        dim3 grid(126, 32, 4);
        scatter_kernel<<<grid, 256>>>(out);
    }
}

// round 16
// speedup vs baseline: 1.1547x; 1.0850x over previous
#include <cuda_runtime.h>
#include <cuda_bf16.h>
#include <cstdint>
#include <math.h>

// Problem constants
static constexpr int Bz   = 32;
static constexpr int INC  = 64;
static constexpr int HIDN = 128;
static constexpr int Gg   = 384;
static constexpr int RR   = 63;
static constexpr int CELLS = RR * RR; // 3969
static constexpr int NCTA_D = 36;     // CTAs per direction (4 kq x 9)
static constexpr int NCTAS  = 144;

// Scratch (allocation-free: __device__ globals)
__device__ float g_gx [(size_t)4 * CELLS * Bz * Gg];    // gx = x@Wx + b   [d][p][q][b][g]
__device__ uint32_t g_hph[(size_t)4 * CELLS * Bz * 64]; // h hi  (bf16x2 k-pair packed) [d][p][q][b][kp]
__device__ uint32_t g_hpm[(size_t)4 * CELLS * Bz * 64]; // h mid residual               [d][p][q][b][kp]
__device__ uint32_t g_Wph[(size_t)4 * 128 * Gg];        // bf16x2 hi of [Wh;Wh2], k-pair packed [d][kp][g]
__device__ uint32_t g_Wpm[(size_t)4 * 128 * Gg];        // bf16x2 mid residual                 [d][kp][g]
__device__ uint32_t g_Wxh[(size_t)4 * 32 * Gg];         // bf16x2 hi of Wx, c-pair packed [d][kp][g]
__device__ uint32_t g_Wxm[(size_t)4 * 32 * Gg];         // bf16x2 mid residual            [d][kp][g]
__device__ uint32_t g_xph[(size_t)4096 * Bz * 32];      // x hi  (bf16x2 c-pair) [i*64+j][b][kp]
__device__ uint32_t g_xpm[(size_t)4096 * Bz * 32];      // x mid residual        [i*64+j][b][kp]
__device__ int          g_bar_count[4];
__device__ volatile int g_bar_gen[4];

// ---------------------------------------------------------------------------
__device__ __forceinline__ unsigned smem_u32(const void* p) {
    return (unsigned)__cvta_generic_to_shared(p);
}
#define CPA16(dst, src) asm volatile("cp.async.cg.shared.global [%0], [%1], 16;" :: "r"(dst), "l"(src))
#define CPC()  asm volatile("cp.async.commit_group;")
#define CPW0() asm volatile("cp.async.wait_group 0;")

#define MMA_BF16(D, a0, a1, a2, a3, bb0, bb1)                                   \
    asm volatile("mma.sync.aligned.m16n8k16.row.col.f32.bf16.bf16.f32 "         \
                 "{%0,%1,%2,%3}, {%4,%5,%6,%7}, {%8,%9}, {%0,%1,%2,%3};"        \
                 : "+f"(D[0]), "+f"(D[1]), "+f"(D[2]), "+f"(D[3])               \
                 : "r"(a0), "r"(a1), "r"(a2), "r"(a3), "r"(bb0), "r"(bb1))

__device__ __forceinline__ float sigf(float x)  { return 1.f / (1.f + __expf(-x)); }
__device__ __forceinline__ float tanhf_fast(float x) {
    float e = __expf(2.f * x);
    return (e - 1.f) / (e + 1.f);
}
__device__ __forceinline__ unsigned pack_bf2(__nv_bfloat16 a, __nv_bfloat16 b) {
    return (unsigned)__bfloat16_as_ushort(a) | ((unsigned)__bfloat16_as_ushort(b) << 16);
}
__device__ __forceinline__ float bf_lo(uint32_t v) {
    return __bfloat162float(__ushort_as_bfloat16((unsigned short)(v & 0xFFFF)));
}
__device__ __forceinline__ float bf_hi(uint32_t v) {
    return __bfloat162float(__ushort_as_bfloat16((unsigned short)(v >> 16)));
}
__device__ __forceinline__ void split2(float a, float b, uint32_t& vh, uint32_t& vm) {
    __nv_bfloat16 ha = __float2bfloat16(a);
    __nv_bfloat16 hb = __float2bfloat16(b);
    vh = pack_bf2(ha, hb);
    vm = pack_bf2(__float2bfloat16(a - __bfloat162float(ha)),
                  __float2bfloat16(b - __bfloat162float(hb)));
}

// ---------------------------------------------------------------------------
// Fill ONLY the uncomputed border cells with 1.0 (one row + one col per dir).
__global__ void __launch_bounds__(256) border_fill_kernel(float* __restrict__ out) {
    const int b = blockIdx.x;
    const int d = blockIdx.y;
    const int row_i = (d & 1) ? 0 : 63;
    const int col_j = (d & 2) ? 0 : 63;
    const int t = threadIdx.x;
    for (int idx = t; idx < 128 * 127; idx += 256) {
        int k = idx / 127;
        int r = idx % 127;
        int i, jj;
        if (r < 64) { i = row_i; jj = r; }
        else {
            int ii = r - 64;                       // 0..62
            i = (ii >= row_i) ? ii + 1 : ii;       // skip row_i
            jj = col_j;
        }
        out[((size_t)(b * 128 + k) * 4 + d) * 4096 + i * 64 + jj] = 1.0f;
    }
}

__global__ void reset_kernel() {
    for (int d = 0; d < 4; d++) { g_bar_count[d] = 0; g_bar_gen[d] = 0; }
}

// ---------------------------------------------------------------------------
// Split [Wh;Wh2] into bf16 hi/mid, packed by k-pairs: g_Wp*[d][kp][g].
__global__ void wsplit_kernel(const float* __restrict__ Wh,
                              const float* __restrict__ Wh2) {
    int i = blockIdx.x * 256 + threadIdx.x;
    int d  = i / (128 * Gg);
    int kp = (i / Gg) % 128;
    int g  = i % Gg;
    int k0 = 2 * kp, k1 = 2 * kp + 1;
    float w0 = (k0 < 128) ? Wh [((size_t)d * 128 + k0) * Gg + g]
                          : Wh2[((size_t)d * 128 + (k0 - 128)) * Gg + g];
    float w1 = (k1 < 128) ? Wh [((size_t)d * 128 + k1) * Gg + g]
                          : Wh2[((size_t)d * 128 + (k1 - 128)) * Gg + g];
    split2(w0, w1, g_Wph[i], g_Wpm[i]);
}

// Split Wx into bf16 hi/mid, packed by c-pairs: g_Wx*[d][kp][g].
__global__ void wxsplit_kernel(const float* __restrict__ Wx) {
    int i = blockIdx.x * 256 + threadIdx.x;   // 4*32*384 = 49152
    int d  = i / (32 * Gg);
    int kp = (i / Gg) % 32;
    int g  = i % Gg;
    float w0 = Wx[((size_t)d * INC + 2 * kp)     * Gg + g];
    float w1 = Wx[((size_t)d * INC + 2 * kp + 1) * Gg + g];
    split2(w0, w1, g_Wxh[i], g_Wxm[i]);
}

// Transpose+split x: x[b][c][i][j] -> g_xp*[i*64+j][b][kp(c/2)] (bf16x2).
__global__ void __launch_bounds__(256) xsplit_kernel(const float* __restrict__ x) {
    const int ij = blockIdx.x;            // 0..4095
    const int t = threadIdx.x;
#pragma unroll
    for (int f0 = 0; f0 < 1024; f0 += 256) {
        int f = f0 + t;
        int b = f >> 5, kp = f & 31;
        float v0 = x[(((size_t)b * INC + 2 * kp)     << 12) + ij];
        float v1 = x[(((size_t)b * INC + 2 * kp + 1) << 12) + ij];
        uint32_t vh, vm;
        split2(v0, v1, vh, vm);
        size_t off = (size_t)ij * (Bz * 32) + f;
        g_xph[off] = vh;
        g_xpm[off] = vm;
    }
}

// ---------------------------------------------------------------------------
// gx via bf16x3 mma (unchanged from R13 WIN).
static constexpr int GXM_PW = 392;
static constexpr int GXM_PA = 36;
static constexpr int GXM_OFF_WH = 0;
static constexpr int GXM_OFF_WM = GXM_OFF_WH + 32 * GXM_PW;
static constexpr int GXM_OFF_AH = GXM_OFF_WM + 32 * GXM_PW;
static constexpr int GXM_OFF_AM = GXM_OFF_AH + 64 * GXM_PA;
static constexpr int GXM_OFF_BIAS = GXM_OFF_AM + 64 * GXM_PA;
static constexpr int GXM_SMEM = (GXM_OFF_BIAS + Gg) * 4;      // 121856 B

__global__ void __launch_bounds__(256) gx_mma_kernel(const float* __restrict__ bias) {
    extern __shared__ uint32_t smu[];
    uint32_t* Wh_s = smu + GXM_OFF_WH;
    uint32_t* Wm_s = smu + GXM_OFF_WM;
    uint32_t* Ah   = smu + GXM_OFF_AH;
    uint32_t* Am   = smu + GXM_OFF_AM;
    float*    bs   = (float*)(smu + GXM_OFF_BIAS);

    const int pair = blockIdx.x;
    const int p    = blockIdx.y;
    const int d    = blockIdx.z;
    const int q0 = 2 * pair;
    const int q1 = q0 + 1;
    const bool c1ok = (q1 < RR);
    const int t = threadIdx.x;
    const int w = t >> 5, lane = t & 31;
    const int gi = lane >> 2, ci = lane & 3;
    const int mp = w >> 2;
    const int ng = w & 3;

    {
        const int ix = (d & 1) ? (62 - p) : p;
        const int jx0 = (d & 2) ? (62 - q0) : q0;
        const int jx1 = (d & 2) ? (62 - q1) : q1;
        const uint32_t* srcs_h[2] = {
            g_xph + (size_t)(ix * 64 + jx0) * 1024,
            g_xph + (size_t)(ix * 64 + jx1) * 1024 };
        const uint32_t* srcs_m[2] = {
            g_xpm + (size_t)(ix * 64 + jx0) * 1024,
            g_xpm + (size_t)(ix * 64 + jx1) * 1024 };
#pragma unroll
        for (int f0 = 0; f0 < 512; f0 += 256) {
            int f = f0 + t;
            int row = f >> 3;
            int kpc = (f & 7) * 4;
            int cl = row >> 5;
            uint32_t* dh = Ah + row * GXM_PA + kpc;
            uint32_t* dm = Am + row * GXM_PA + kpc;
            if (cl == 0 || c1ok) {
                int srcoff = (row & 31) * 32 + kpc;
                CPA16(smem_u32(dh), srcs_h[cl] + srcoff);
                CPA16(smem_u32(dm), srcs_m[cl] + srcoff);
            } else {
                *(uint4*)dh = make_uint4(0u, 0u, 0u, 0u);
                *(uint4*)dm = make_uint4(0u, 0u, 0u, 0u);
            }
        }
        for (int f = t; f < 32 * 96; f += 256) {
            int kp = f / 96, c16 = (f % 96) * 4;
            size_t gsrc = ((size_t)d * 32 + kp) * Gg + c16;
            CPA16(smem_u32(Wh_s + kp * GXM_PW + c16), g_Wxh + gsrc);
            CPA16(smem_u32(Wm_s + kp * GXM_PW + c16), g_Wxm + gsrc);
        }
        for (int f = t; f < Gg / 4; f += 256) {
            CPA16(smem_u32(bs + f * 4), bias + (size_t)d * Gg + f * 4);
        }
        CPC(); CPW0();
        __syncthreads();
    }

    float acc[2][12][4];
#pragma unroll
    for (int mt = 0; mt < 2; mt++)
#pragma unroll
        for (int nn = 0; nn < 12; nn++)
#pragma unroll
            for (int v = 0; v < 4; v++) acc[mt][nn][v] = 0.f;

    const uint32_t* AhRow = Ah + (mp * 32 + gi) * GXM_PA;
    const uint32_t* AmRow = Am + (mp * 32 + gi) * GXM_PA;

#pragma unroll
    for (int k16 = 0; k16 < 4; k16++) {
        const int kp0 = k16 * 8;
        unsigned ahf[2][4], amf[2][4];
#pragma unroll
        for (int mt = 0; mt < 2; mt++) {
            const uint32_t* Ah0 = AhRow + mt * 16 * GXM_PA + kp0;
            const uint32_t* Am0 = AmRow + mt * 16 * GXM_PA + kp0;
            ahf[mt][0] = Ah0[ci];     ahf[mt][1] = Ah0[8 * GXM_PA + ci];
            ahf[mt][2] = Ah0[ci + 4]; ahf[mt][3] = Ah0[8 * GXM_PA + ci + 4];
            amf[mt][0] = Am0[ci];     amf[mt][1] = Am0[8 * GXM_PA + ci];
            amf[mt][2] = Am0[ci + 4]; amf[mt][3] = Am0[8 * GXM_PA + ci + 4];
        }
#pragma unroll
        for (int nn = 0; nn < 12; nn++) {
            const int c = ng * 96 + nn * 8 + gi;
            unsigned bh0 = Wh_s[(kp0 + ci) * GXM_PW + c];
            unsigned bh1 = Wh_s[(kp0 + ci + 4) * GXM_PW + c];
            unsigned bm0 = Wm_s[(kp0 + ci) * GXM_PW + c];
            unsigned bm1 = Wm_s[(kp0 + ci + 4) * GXM_PW + c];
#pragma unroll
            for (int mt = 0; mt < 2; mt++) {
                MMA_BF16(acc[mt][nn], ahf[mt][0], ahf[mt][1], ahf[mt][2], ahf[mt][3], bh0, bh1);
                MMA_BF16(acc[mt][nn], amf[mt][0], amf[mt][1], amf[mt][2], amf[mt][3], bh0, bh1);
                MMA_BF16(acc[mt][nn], ahf[mt][0], ahf[mt][1], ahf[mt][2], ahf[mt][3], bm0, bm1);
            }
        }
    }

    if (!(mp == 1 && !c1ok)) {
        const size_t cell = (size_t)d * CELLS + (size_t)p * RR + (mp ? q1 : q0);
#pragma unroll
        for (int mt = 0; mt < 2; mt++) {
#pragma unroll
            for (int half = 0; half < 2; half++) {
                const int b = mt * 16 + half * 8 + gi;
                float* gp = g_gx + (cell * Bz + b) * Gg;
#pragma unroll
                for (int nn = 0; nn < 12; nn++) {
                    const int col = ng * 96 + nn * 8 + 2 * ci;
                    float2 v = make_float2(acc[mt][nn][half * 2 + 0] + bs[col],
                                           acc[mt][nn][half * 2 + 1] + bs[col + 1]);
                    *(float2*)(gp + col) = v;
                }
            }
        }
    }
}

// ---------------------------------------------------------------------------
// Persistent bf16x3 wavefront scan (R15 skeleton) + hoisted gx loads:
// the epilogue's 12 gx float2 loads are issued BEFORE the MMA mainloop so
// their L2 latency hides under the ~2.4us of MMAs.
static constexpr int PAD_W = 104;    // u32 per W row (96 + 8; 8ci+gi bijective)
static constexpr int PAD_T = 68;     // u32 per tile row (64 + 4; 4gi+ci bijective)
static constexpr int TILE_W = 32 * PAD_T;             // 2176 u32
static constexpr int OFF_WPH = 0;                     // [128][104]
static constexpr int OFF_WPM = OFF_WPH + 128 * PAD_W; // [128][104]
static constexpr int OFF_T   = OFF_WPM + 128 * PAD_W; // [2 buf][2 hm][3 tile][2176]
static constexpr int SCAN_SMEM = (OFF_T + 2 * 2 * 3 * TILE_W) * 4;  // 210944 B

__device__ __forceinline__ void grid_barrier_d(int d, int gen) {
    __syncthreads();
    if (threadIdx.x == 0) {
        __threadfence();
        if (atomicAdd(&g_bar_count[d], 1) == NCTA_D - 1) {
            g_bar_count[d] = 0;
            __threadfence();
            g_bar_gen[d] = gen;
        } else {
            while (g_bar_gen[d] < gen) { __nanosleep(32); }
            __threadfence();
        }
    }
    __syncthreads();
}

__global__ void __launch_bounds__(256, 1) scan_persist_kernel() {
    extern __shared__ uint32_t smu[];
    uint32_t* Wph_s = smu + OFF_WPH;
    uint32_t* Wpm_s = smu + OFF_WPM;

    const int cta = blockIdx.x;
    const int d  = cta / 36;
    const int kq = (cta / 9) % 4;
    const int j  = cta % 9;
    const int t  = threadIdx.x;
    const int w = t >> 5, lane = t & 31;
    const int gi = lane >> 2, ci = lane & 3;
    const int mp = w >> 2;      // cell within pair
    const int ng = w & 3;       // n8 group within each gate's 32 cols
    const size_t dBase = (size_t)d * CELLS;

    // ---- one-time weight staging: col c = gate*32 + koff; kp rows 0..127 ----
    for (int idx = t; idx < 128 * 96; idx += 256) {
        int kp = idx / 96, c = idx % 96;
        int gcol = (c >> 5) * 128 + kq * 32 + (c & 31);
        size_t gsrc = ((size_t)d * 128 + kp) * Gg + gcol;
        Wph_s[kp * PAD_W + c] = g_Wph[gsrc];
        Wpm_s[kp * PAD_W + c] = g_Wpm[gsrc];
    }
    __syncthreads();

    for (int s = 0; s < 2 * RR - 1; s++) {
        const int qlo = (s - (RR - 1) > 0) ? (s - (RR - 1)) : 0;
        const int qhi = (s < RR - 1) ? s : (RR - 1);
        const int npairs = (qhi - qlo + 2) >> 1;

        // stage task pi_'s 3 tiles (up0, lf0, up1) into buffer buf_
        auto stageA = [&](int pi_, int buf_) {
            const int q0_ = qlo + 2 * pi_;
            const int q1_ = q0_ + 1;
            const bool c1_ = (q1_ <= qhi);
            const int p0_ = s - q0_;
            const int p1_ = s - q1_;
            const size_t c0_ = dBase + (size_t)p0_ * RR + q0_;
            const size_t c1_c = dBase + (size_t)p1_ * RR + q1_;
            bool val[3];
            size_t srcC[3];
            val[0] = (p0_ > 0);          srcC[0] = c0_ - RR;   // up0 (== lf1)
            val[1] = (q0_ > 0);          srcC[1] = c0_ - 1;    // lf0
            val[2] = c1_ && (p1_ > 0);   srcC[2] = c1_c - RR;  // up1
            uint32_t* baseH = smu + OFF_T + buf_ * (6 * TILE_W);
#pragma unroll
            for (int f0 = 0; f0 < 1536; f0 += 256) {
                const int f = f0 + t;
                const int tl  = f >> 9;          // tile 0..2
                const int row = (f >> 4) & 31;   // batch row
                const int ch  = f & 15;          // 16B chunk (4 u32)
                uint32_t* dh = baseH + tl * TILE_W + row * PAD_T + ch * 4;
                uint32_t* dm = dh + 3 * TILE_W;
                if (val[tl]) {
                    size_t off = (srcC[tl] * Bz + row) * 64 + ch * 4;
                    CPA16(smem_u32(dh), g_hph + off);
                    CPA16(smem_u32(dm), g_hpm + off);
                } else {
                    *(uint4*)dh = make_uint4(0u, 0u, 0u, 0u);
                    *(uint4*)dm = make_uint4(0u, 0u, 0u, 0u);
                }
            }
        };

        int buf = 0;
        bool havePrefetch = false;

        for (int pi = j; pi < npairs; pi += 9) {
            const int q0 = qlo + 2 * pi;
            const int q1 = q0 + 1;
            const bool c1ok = (q1 <= qhi);
            const int p1 = s - q1;
            const size_t cell0 = dBase + (size_t)(s - q0) * RR + q0;
            const size_t cell1 = dBase + (size_t)p1 * RR + q1;

            if (!havePrefetch) { stageA(pi, buf); CPC(); }
            CPW0();
            __syncthreads();

            // prefetch next task on this diagonal into the other buffer
            const bool nxt = (pi + 9 < npairs);
            if (nxt) { stageA(pi + 9, buf ^ 1); CPC(); }

            // ---- hoisted gx loads (latency hides under the MMA mainloop) ----
            const bool doepi = !(mp == 1 && !c1ok);
            const size_t cellE = mp ? cell1 : cell0;
            const int kbase = kq * 32 + ng * 8 + 2 * ci;
            float2 grv[2][2], gzv[2][2], gnv[2][2];
            if (doepi) {
#pragma unroll
                for (int mt = 0; mt < 2; mt++) {
#pragma unroll
                    for (int half = 0; half < 2; half++) {
                        const int b = mt * 16 + half * 8 + gi;
                        const float* gxc = g_gx + (cellE * Bz + b) * Gg;
                        grv[mt][half] = __ldcg((const float2*)(gxc + kbase));
                        gzv[mt][half] = __ldcg((const float2*)(gxc + 128 + kbase));
                        gnv[mt][half] = __ldcg((const float2*)(gxc + 256 + kbase));
                    }
                }
            }

            uint32_t* bufBase = smu + OFF_T + buf * (6 * TILE_W);

            // ---- bf16x3 MMA mainloop over K=256 (2 halves x 8 k16) ----
            float acc[2][3][4];
#pragma unroll
            for (int mt = 0; mt < 2; mt++)
#pragma unroll
                for (int g = 0; g < 3; g++)
#pragma unroll
                    for (int v = 0; v < 4; v++) acc[mt][g][v] = 0.f;

            const int cb0 = ng * 8 + gi;
            // warp tile selection: half0 = up (cell0->T0, cell1->T2);
            //                      half1 = left (cell0->T1, cell1->T0)
            const uint32_t* AhT[2] = {
                bufBase + (mp ? 2 : 0) * TILE_W,
                bufBase + (mp ? 0 : 1) * TILE_W };

#pragma unroll
            for (int half = 0; half < 2; half++) {
                const uint32_t* Aht = AhT[half];
                const uint32_t* Amt = Aht + 3 * TILE_W;
#pragma unroll 4
                for (int k8 = 0; k8 < 8; k8++) {
                    const int kpl = k8 * 8;              // kp within tile
                    const int kpw = half * 64 + kpl;     // W row
                    unsigned bh[3][2], bm[3][2];
#pragma unroll
                    for (int g = 0; g < 3; g++) {
                        const int c = g * 32 + cb0;
                        bh[g][0] = Wph_s[(kpw + ci) * PAD_W + c];
                        bh[g][1] = Wph_s[(kpw + ci + 4) * PAD_W + c];
                        bm[g][0] = Wpm_s[(kpw + ci) * PAD_W + c];
                        bm[g][1] = Wpm_s[(kpw + ci + 4) * PAD_W + c];
                    }
#pragma unroll
                    for (int mt = 0; mt < 2; mt++) {
                        const uint32_t* Ah0 = Aht + (mt * 16 + gi) * PAD_T + kpl;
                        const uint32_t* Am0 = Amt + (mt * 16 + gi) * PAD_T + kpl;
                        unsigned ah0 = Ah0[ci],     ah1 = Ah0[8 * PAD_T + ci];
                        unsigned ah2 = Ah0[ci + 4], ah3 = Ah0[8 * PAD_T + ci + 4];
                        unsigned am0 = Am0[ci],     am1 = Am0[8 * PAD_T + ci];
                        unsigned am2 = Am0[ci + 4], am3 = Am0[8 * PAD_T + ci + 4];
#pragma unroll
                        for (int g = 0; g < 3; g++) {
                            MMA_BF16(acc[mt][g], ah0, ah1, ah2, ah3, bh[g][0], bh[g][1]);
                            MMA_BF16(acc[mt][g], am0, am1, am2, am3, bh[g][0], bh[g][1]);
                            MMA_BF16(acc[mt][g], ah0, ah1, ah2, ah3, bm[g][0], bm[g][1]);
                        }
                    }
                }
            }

            // ---- GRU epilogue: warp's cell = mp; store pre-split h ----
            if (doepi) {
                const uint32_t* huT = bufBase + (mp ? 2 : 0) * TILE_W;  // up
                const uint32_t* hlT = bufBase + (mp ? 0 : 1) * TILE_W;  // left
                const uint32_t* huTm = huT + 3 * TILE_W;
                const uint32_t* hlTm = hlT + 3 * TILE_W;
                const int kp = kbase >> 1;
#pragma unroll
                for (int mt = 0; mt < 2; mt++) {
#pragma unroll
                    for (int half = 0; half < 2; half++) {
                        const int b = mt * 16 + half * 8 + gi;
                        float2 gr = grv[mt][half];
                        float2 gz = gzv[mt][half];
                        float2 gn = gnv[mt][half];
                        uint32_t huH = huT [b * PAD_T + kp];
                        uint32_t huM = huTm[b * PAD_T + kp];
                        uint32_t hlH = hlT [b * PAD_T + kp];
                        uint32_t hlM = hlTm[b * PAD_T + kp];
                        float hu0 = bf_lo(huH) + bf_lo(huM);
                        float hu1 = bf_hi(huH) + bf_hi(huM);
                        float hl0 = bf_lo(hlH) + bf_lo(hlM);
                        float hl1 = bf_hi(hlH) + bf_hi(hlM);
                        float r0 = sigf(acc[mt][0][half * 2 + 0] + gr.x);
                        float r1 = sigf(acc[mt][0][half * 2 + 1] + gr.y);
                        float z0 = sigf(acc[mt][1][half * 2 + 0] + gz.x);
                        float z1 = sigf(acc[mt][1][half * 2 + 1] + gz.y);
                        float n0 = tanhf_fast(gn.x + r0 * acc[mt][2][half * 2 + 0]);
                        float n1 = tanhf_fast(gn.y + r1 * acc[mt][2][half * 2 + 1]);
                        float h0 = (1.f - z0) * n0 + z0 * 0.5f * (hu0 + hl0);
                        float h1 = (1.f - z1) * n1 + z1 * 0.5f * (hu1 + hl1);
                        uint32_t vh, vm;
                        split2(h0, h1, vh, vm);
                        size_t off = (cellE * Bz + b) * 64 + kp;
                        g_hph[off] = vh;
                        g_hpm[off] = vm;
                    }
                }
            }
            __syncthreads();   // epilogue reads done before buffer reuse
            buf ^= 1;
            havePrefetch = nxt;
        }

        grid_barrier_d(d, s + 1);
    }
}

// ---------------------------------------------------------------------------
// Post-scan scatter (unchanged from R12 WIN).
__global__ void __launch_bounds__(256) scatter_kernel(float* __restrict__ out) {
    __shared__ float sm[32][129];
    const int bx = blockIdx.x;
    const int b  = blockIdx.y;
    const int d  = blockIdx.z;
    const int p  = bx >> 1;
    const int qt = bx & 1;
    const int qb = qt * 32;
    const int nq = qt ? 31 : 32;
    const int t  = threadIdx.x;

    for (int idx = t; idx < nq * 64; idx += 256) {
        const int qi = idx >> 6;
        const int kp = idx & 63;
        const size_t cell = (size_t)d * CELLS + (size_t)p * RR + (qb + qi);
        const size_t off = (cell * Bz + b) * 64 + kp;
        uint32_t vh = g_hph[off];
        uint32_t vm = g_hpm[off];
        sm[qi][2 * kp]     = bf_lo(vh) + bf_lo(vm);
        sm[qi][2 * kp + 1] = bf_hi(vh) + bf_hi(vm);
    }
    __syncthreads();

    const int oi = (d & 1) ? (63 - p) : p;
    for (int idx = t; idx < 32 * 128; idx += 256) {
        const int k  = idx >> 5;
        const int qi = idx & 31;
        if (qi < nq) {
            const int q  = qb + qi;
            const int oj = (d & 2) ? (63 - q) : q;
            out[((size_t)(b * 128 + k) * 4 + d) * 4096 + (size_t)oi * 64 + oj]
                = sm[qi][k];
        }
    }
}

// ---------------------------------------------------------------------------
extern "C" void kernel_launch(void* const* d_in, const int* in_sizes, int n_in,
                              void* d_out, int out_size) {
    const float* x    = (const float*)d_in[0];
    const float* Wx   = (const float*)d_in[1];
    const float* Wh   = (const float*)d_in[2];
    const float* Wh2  = (const float*)d_in[3];
    const float* bias = (const float*)d_in[4];
    float* out = (float*)d_out;

    cudaFuncSetAttribute(gx_mma_kernel,
                         cudaFuncAttributeMaxDynamicSharedMemorySize, GXM_SMEM);
    cudaFuncSetAttribute(scan_persist_kernel,
                         cudaFuncAttributeMaxDynamicSharedMemorySize, SCAN_SMEM);

    // 1) independent prep
    {
        dim3 grid(32, 4);
        border_fill_kernel<<<grid, 256>>>(out);
    }
    wsplit_kernel<<<768, 256>>>(Wh, Wh2);
    wxsplit_kernel<<<192, 256>>>(Wx);
    xsplit_kernel<<<4096, 256>>>(x);
    reset_kernel<<<1, 1>>>();

    // 2) gx via bf16x3 mma
    {
        dim3 grid(32, 63, 4);
        gx_mma_kernel<<<grid, 256, GXM_SMEM>>>(bias);
    }

    // 3) persistent bf16x3 wavefront scan (grid barrier + prefetch + gx hoist)
    scan_persist_kernel<<<NCTAS, 256, SCAN_SMEM>>>();

    // 4) coalesced transpose of h into the output layout
    {
        dim3 grid(126, 32, 4);
        scatter_kernel<<<grid, 256>>>(out);
    }
}

// round 17
// speedup vs baseline: 1.1655x; 1.0093x over previous
#include <cuda_runtime.h>
#include <cuda_bf16.h>
#include <cstdint>
#include <math.h>

// Problem constants
static constexpr int Bz   = 32;
static constexpr int INC  = 64;
static constexpr int HIDN = 128;
static constexpr int Gg   = 384;
static constexpr int RR   = 63;
static constexpr int CELLS = RR * RR; // 3969
static constexpr int NCTA_D = 36;     // CTAs per direction (4 kq x 9)
static constexpr int NCTAS  = 144;

// Scratch (allocation-free: __device__ globals)
__device__ float g_gx [(size_t)4 * CELLS * Bz * Gg];    // gx = x@Wx + b   [d][p][q][b][g]
__device__ uint32_t g_hph[(size_t)4 * CELLS * Bz * 64]; // h hi  (bf16x2 k-pair packed) [d][p][q][b][kp]
__device__ uint32_t g_hpm[(size_t)4 * CELLS * Bz * 64]; // h mid residual               [d][p][q][b][kp]
__device__ uint32_t g_Wph[(size_t)4 * 128 * Gg];        // bf16x2 hi of [Wh;Wh2], k-pair packed [d][kp][g]
__device__ uint32_t g_Wpm[(size_t)4 * 128 * Gg];        // bf16x2 mid residual                 [d][kp][g]
__device__ uint32_t g_Wxh[(size_t)4 * 32 * Gg];         // bf16x2 hi of Wx, c-pair packed [d][kp][g]
__device__ uint32_t g_Wxm[(size_t)4 * 32 * Gg];         // bf16x2 mid residual            [d][kp][g]
__device__ uint32_t g_xph[(size_t)4096 * Bz * 32];      // x hi  (bf16x2 c-pair) [i*64+j][b][kp]
__device__ uint32_t g_xpm[(size_t)4096 * Bz * 32];      // x mid residual        [i*64+j][b][kp]
__device__ int          g_bar_count[4];
__device__ volatile int g_bar_gen[4];

// ---------------------------------------------------------------------------
__device__ __forceinline__ unsigned smem_u32(const void* p) {
    return (unsigned)__cvta_generic_to_shared(p);
}
#define CPA16(dst, src) asm volatile("cp.async.cg.shared.global [%0], [%1], 16;" :: "r"(dst), "l"(src))
#define CPC()  asm volatile("cp.async.commit_group;")
#define CPW0() asm volatile("cp.async.wait_group 0;")

#define MMA_BF16(D, a0, a1, a2, a3, bb0, bb1)                                   \
    asm volatile("mma.sync.aligned.m16n8k16.row.col.f32.bf16.bf16.f32 "         \
                 "{%0,%1,%2,%3}, {%4,%5,%6,%7}, {%8,%9}, {%0,%1,%2,%3};"        \
                 : "+f"(D[0]), "+f"(D[1]), "+f"(D[2]), "+f"(D[3])               \
                 : "r"(a0), "r"(a1), "r"(a2), "r"(a3), "r"(bb0), "r"(bb1))

#define LDSM4(r0, r1, r2, r3, addr)                                             \
    asm volatile("ldmatrix.sync.aligned.m8n8.x4.shared.b16 {%0,%1,%2,%3}, [%4];" \
                 : "=r"(r0), "=r"(r1), "=r"(r2), "=r"(r3) : "r"(addr))

__device__ __forceinline__ float sigf(float x)  { return 1.f / (1.f + __expf(-x)); }
__device__ __forceinline__ float tanhf_fast(float x) {
    float e = __expf(2.f * x);
    return (e - 1.f) / (e + 1.f);
}
__device__ __forceinline__ unsigned pack_bf2(__nv_bfloat16 a, __nv_bfloat16 b) {
    return (unsigned)__bfloat16_as_ushort(a) | ((unsigned)__bfloat16_as_ushort(b) << 16);
}
__device__ __forceinline__ float bf_lo(uint32_t v) {
    return __bfloat162float(__ushort_as_bfloat16((unsigned short)(v & 0xFFFF)));
}
__device__ __forceinline__ float bf_hi(uint32_t v) {
    return __bfloat162float(__ushort_as_bfloat16((unsigned short)(v >> 16)));
}
__device__ __forceinline__ void split2(float a, float b, uint32_t& vh, uint32_t& vm) {
    __nv_bfloat16 ha = __float2bfloat16(a);
    __nv_bfloat16 hb = __float2bfloat16(b);
    vh = pack_bf2(ha, hb);
    vm = pack_bf2(__float2bfloat16(a - __bfloat162float(ha)),
                  __float2bfloat16(b - __bfloat162float(hb)));
}

// ---------------------------------------------------------------------------
// Fill ONLY the uncomputed border cells with 1.0 (one row + one col per dir).
__global__ void __launch_bounds__(256) border_fill_kernel(float* __restrict__ out) {
    const int b = blockIdx.x;
    const int d = blockIdx.y;
    const int row_i = (d & 1) ? 0 : 63;
    const int col_j = (d & 2) ? 0 : 63;
    const int t = threadIdx.x;
    for (int idx = t; idx < 128 * 127; idx += 256) {
        int k = idx / 127;
        int r = idx % 127;
        int i, jj;
        if (r < 64) { i = row_i; jj = r; }
        else {
            int ii = r - 64;                       // 0..62
            i = (ii >= row_i) ? ii + 1 : ii;       // skip row_i
            jj = col_j;
        }
        out[((size_t)(b * 128 + k) * 4 + d) * 4096 + i * 64 + jj] = 1.0f;
    }
}

__global__ void reset_kernel() {
    for (int d = 0; d < 4; d++) { g_bar_count[d] = 0; g_bar_gen[d] = 0; }
}

// ---------------------------------------------------------------------------
// Split [Wh;Wh2] into bf16 hi/mid, packed by k-pairs: g_Wp*[d][kp][g].
__global__ void wsplit_kernel(const float* __restrict__ Wh,
                              const float* __restrict__ Wh2) {
    int i = blockIdx.x * 256 + threadIdx.x;
    int d  = i / (128 * Gg);
    int kp = (i / Gg) % 128;
    int g  = i % Gg;
    int k0 = 2 * kp, k1 = 2 * kp + 1;
    float w0 = (k0 < 128) ? Wh [((size_t)d * 128 + k0) * Gg + g]
                          : Wh2[((size_t)d * 128 + (k0 - 128)) * Gg + g];
    float w1 = (k1 < 128) ? Wh [((size_t)d * 128 + k1) * Gg + g]
                          : Wh2[((size_t)d * 128 + (k1 - 128)) * Gg + g];
    split2(w0, w1, g_Wph[i], g_Wpm[i]);
}

// Split Wx into bf16 hi/mid, packed by c-pairs: g_Wx*[d][kp][g].
__global__ void wxsplit_kernel(const float* __restrict__ Wx) {
    int i = blockIdx.x * 256 + threadIdx.x;   // 4*32*384 = 49152
    int d  = i / (32 * Gg);
    int kp = (i / Gg) % 32;
    int g  = i % Gg;
    float w0 = Wx[((size_t)d * INC + 2 * kp)     * Gg + g];
    float w1 = Wx[((size_t)d * INC + 2 * kp + 1) * Gg + g];
    split2(w0, w1, g_Wxh[i], g_Wxm[i]);
}

// Transpose+split x: x[b][c][i][j] -> g_xp*[i*64+j][b][kp(c/2)] (bf16x2).
__global__ void __launch_bounds__(256) xsplit_kernel(const float* __restrict__ x) {
    const int ij = blockIdx.x;            // 0..4095
    const int t = threadIdx.x;
#pragma unroll
    for (int f0 = 0; f0 < 1024; f0 += 256) {
        int f = f0 + t;
        int b = f >> 5, kp = f & 31;
        float v0 = x[(((size_t)b * INC + 2 * kp)     << 12) + ij];
        float v1 = x[(((size_t)b * INC + 2 * kp + 1) << 12) + ij];
        uint32_t vh, vm;
        split2(v0, v1, vh, vm);
        size_t off = (size_t)ij * (Bz * 32) + f;
        g_xph[off] = vh;
        g_xpm[off] = vm;
    }
}

// ---------------------------------------------------------------------------
// gx via bf16x3 mma (unchanged from R13 WIN).
static constexpr int GXM_PW = 392;
static constexpr int GXM_PA = 36;
static constexpr int GXM_OFF_WH = 0;
static constexpr int GXM_OFF_WM = GXM_OFF_WH + 32 * GXM_PW;
static constexpr int GXM_OFF_AH = GXM_OFF_WM + 32 * GXM_PW;
static constexpr int GXM_OFF_AM = GXM_OFF_AH + 64 * GXM_PA;
static constexpr int GXM_OFF_BIAS = GXM_OFF_AM + 64 * GXM_PA;
static constexpr int GXM_SMEM = (GXM_OFF_BIAS + Gg) * 4;      // 121856 B

__global__ void __launch_bounds__(256) gx_mma_kernel(const float* __restrict__ bias) {
    extern __shared__ uint32_t smu[];
    uint32_t* Wh_s = smu + GXM_OFF_WH;
    uint32_t* Wm_s = smu + GXM_OFF_WM;
    uint32_t* Ah   = smu + GXM_OFF_AH;
    uint32_t* Am   = smu + GXM_OFF_AM;
    float*    bs   = (float*)(smu + GXM_OFF_BIAS);

    const int pair = blockIdx.x;
    const int p    = blockIdx.y;
    const int d    = blockIdx.z;
    const int q0 = 2 * pair;
    const int q1 = q0 + 1;
    const bool c1ok = (q1 < RR);
    const int t = threadIdx.x;
    const int w = t >> 5, lane = t & 31;
    const int gi = lane >> 2, ci = lane & 3;
    const int mp = w >> 2;
    const int ng = w & 3;

    {
        const int ix = (d & 1) ? (62 - p) : p;
        const int jx0 = (d & 2) ? (62 - q0) : q0;
        const int jx1 = (d & 2) ? (62 - q1) : q1;
        const uint32_t* srcs_h[2] = {
            g_xph + (size_t)(ix * 64 + jx0) * 1024,
            g_xph + (size_t)(ix * 64 + jx1) * 1024 };
        const uint32_t* srcs_m[2] = {
            g_xpm + (size_t)(ix * 64 + jx0) * 1024,
            g_xpm + (size_t)(ix * 64 + jx1) * 1024 };
#pragma unroll
        for (int f0 = 0; f0 < 512; f0 += 256) {
            int f = f0 + t;
            int row = f >> 3;
            int kpc = (f & 7) * 4;
            int cl = row >> 5;
            uint32_t* dh = Ah + row * GXM_PA + kpc;
            uint32_t* dm = Am + row * GXM_PA + kpc;
            if (cl == 0 || c1ok) {
                int srcoff = (row & 31) * 32 + kpc;
                CPA16(smem_u32(dh), srcs_h[cl] + srcoff);
                CPA16(smem_u32(dm), srcs_m[cl] + srcoff);
            } else {
                *(uint4*)dh = make_uint4(0u, 0u, 0u, 0u);
                *(uint4*)dm = make_uint4(0u, 0u, 0u, 0u);
            }
        }
        for (int f = t; f < 32 * 96; f += 256) {
            int kp = f / 96, c16 = (f % 96) * 4;
            size_t gsrc = ((size_t)d * 32 + kp) * Gg + c16;
            CPA16(smem_u32(Wh_s + kp * GXM_PW + c16), g_Wxh + gsrc);
            CPA16(smem_u32(Wm_s + kp * GXM_PW + c16), g_Wxm + gsrc);
        }
        for (int f = t; f < Gg / 4; f += 256) {
            CPA16(smem_u32(bs + f * 4), bias + (size_t)d * Gg + f * 4);
        }
        CPC(); CPW0();
        __syncthreads();
    }

    float acc[2][12][4];
#pragma unroll
    for (int mt = 0; mt < 2; mt++)
#pragma unroll
        for (int nn = 0; nn < 12; nn++)
#pragma unroll
            for (int v = 0; v < 4; v++) acc[mt][nn][v] = 0.f;

    const uint32_t* AhRow = Ah + (mp * 32 + gi) * GXM_PA;
    const uint32_t* AmRow = Am + (mp * 32 + gi) * GXM_PA;

#pragma unroll
    for (int k16 = 0; k16 < 4; k16++) {
        const int kp0 = k16 * 8;
        unsigned ahf[2][4], amf[2][4];
#pragma unroll
        for (int mt = 0; mt < 2; mt++) {
            const uint32_t* Ah0 = AhRow + mt * 16 * GXM_PA + kp0;
            const uint32_t* Am0 = AmRow + mt * 16 * GXM_PA + kp0;
            ahf[mt][0] = Ah0[ci];     ahf[mt][1] = Ah0[8 * GXM_PA + ci];
            ahf[mt][2] = Ah0[ci + 4]; ahf[mt][3] = Ah0[8 * GXM_PA + ci + 4];
            amf[mt][0] = Am0[ci];     amf[mt][1] = Am0[8 * GXM_PA + ci];
            amf[mt][2] = Am0[ci + 4]; amf[mt][3] = Am0[8 * GXM_PA + ci + 4];
        }
#pragma unroll
        for (int nn = 0; nn < 12; nn++) {
            const int c = ng * 96 + nn * 8 + gi;
            unsigned bh0 = Wh_s[(kp0 + ci) * GXM_PW + c];
            unsigned bh1 = Wh_s[(kp0 + ci + 4) * GXM_PW + c];
            unsigned bm0 = Wm_s[(kp0 + ci) * GXM_PW + c];
            unsigned bm1 = Wm_s[(kp0 + ci + 4) * GXM_PW + c];
#pragma unroll
            for (int mt = 0; mt < 2; mt++) {
                MMA_BF16(acc[mt][nn], ahf[mt][0], ahf[mt][1], ahf[mt][2], ahf[mt][3], bh0, bh1);
                MMA_BF16(acc[mt][nn], amf[mt][0], amf[mt][1], amf[mt][2], amf[mt][3], bh0, bh1);
                MMA_BF16(acc[mt][nn], ahf[mt][0], ahf[mt][1], ahf[mt][2], ahf[mt][3], bm0, bm1);
            }
        }
    }

    if (!(mp == 1 && !c1ok)) {
        const size_t cell = (size_t)d * CELLS + (size_t)p * RR + (mp ? q1 : q0);
#pragma unroll
        for (int mt = 0; mt < 2; mt++) {
#pragma unroll
            for (int half = 0; half < 2; half++) {
                const int b = mt * 16 + half * 8 + gi;
                float* gp = g_gx + (cell * Bz + b) * Gg;
#pragma unroll
                for (int nn = 0; nn < 12; nn++) {
                    const int col = ng * 96 + nn * 8 + 2 * ci;
                    float2 v = make_float2(acc[mt][nn][half * 2 + 0] + bs[col],
                                           acc[mt][nn][half * 2 + 1] + bs[col + 1]);
                    *(float2*)(gp + col) = v;
                }
            }
        }
    }
}

// ---------------------------------------------------------------------------
// Persistent bf16x3 wavefront scan (R16 skeleton) +
//  - ldmatrix.x4 A-fragment loads (16 LDS -> 4 LDSM per k8)
//  - hu/hl hoisted into registers (epilogue = pure register + STG)
//  - trailing __syncthreads removed (ordering via next CPW0+sync)
static constexpr int PAD_W = 104;    // u32 per W row (96 + 8; 8ci+gi bijective)
static constexpr int PAD_T = 68;     // u32 per tile row (64 + 4)
static constexpr int TILE_W = 32 * PAD_T;             // 2176 u32
static constexpr int OFF_WPH = 0;                     // [128][104]
static constexpr int OFF_WPM = OFF_WPH + 128 * PAD_W; // [128][104]
static constexpr int OFF_T   = OFF_WPM + 128 * PAD_W; // [2 buf][2 hm][3 tile][2176]
static constexpr int SCAN_SMEM = (OFF_T + 2 * 2 * 3 * TILE_W) * 4;  // 210944 B

__device__ __forceinline__ void grid_barrier_d(int d, int gen) {
    __syncthreads();
    if (threadIdx.x == 0) {
        __threadfence();
        if (atomicAdd(&g_bar_count[d], 1) == NCTA_D - 1) {
            g_bar_count[d] = 0;
            __threadfence();
            g_bar_gen[d] = gen;
        } else {
            while (g_bar_gen[d] < gen) { __nanosleep(32); }
            __threadfence();
        }
    }
    __syncthreads();
}

__global__ void __launch_bounds__(256, 1) scan_persist_kernel() {
    extern __shared__ uint32_t smu[];
    uint32_t* Wph_s = smu + OFF_WPH;
    uint32_t* Wpm_s = smu + OFF_WPM;

    const int cta = blockIdx.x;
    const int d  = cta / 36;
    const int kq = (cta / 9) % 4;
    const int j  = cta % 9;
    const int t  = threadIdx.x;
    const int w = t >> 5, lane = t & 31;
    const int gi = lane >> 2, ci = lane & 3;
    const int mp = w >> 2;      // cell within pair
    const int ng = w & 3;       // n8 group within each gate's 32 cols
    const size_t dBase = (size_t)d * CELLS;

    // ldmatrix per-lane addressing: row = lane&15, k-offset = (lane>>4)*4 u32
    const int ldm_row  = lane & 15;
    const int ldm_koff = (lane >> 4) * 4;

    // ---- one-time weight staging: col c = gate*32 + koff; kp rows 0..127 ----
    for (int idx = t; idx < 128 * 96; idx += 256) {
        int kp = idx / 96, c = idx % 96;
        int gcol = (c >> 5) * 128 + kq * 32 + (c & 31);
        size_t gsrc = ((size_t)d * 128 + kp) * Gg + gcol;
        Wph_s[kp * PAD_W + c] = g_Wph[gsrc];
        Wpm_s[kp * PAD_W + c] = g_Wpm[gsrc];
    }
    __syncthreads();

    for (int s = 0; s < 2 * RR - 1; s++) {
        const int qlo = (s - (RR - 1) > 0) ? (s - (RR - 1)) : 0;
        const int qhi = (s < RR - 1) ? s : (RR - 1);
        const int npairs = (qhi - qlo + 2) >> 1;

        // stage task pi_'s 3 tiles (up0, lf0, up1) into buffer buf_
        auto stageA = [&](int pi_, int buf_) {
            const int q0_ = qlo + 2 * pi_;
            const int q1_ = q0_ + 1;
            const bool c1_ = (q1_ <= qhi);
            const int p0_ = s - q0_;
            const int p1_ = s - q1_;
            const size_t c0_ = dBase + (size_t)p0_ * RR + q0_;
            const size_t c1_c = dBase + (size_t)p1_ * RR + q1_;
            bool val[3];
            size_t srcC[3];
            val[0] = (p0_ > 0);          srcC[0] = c0_ - RR;   // up0 (== lf1)
            val[1] = (q0_ > 0);          srcC[1] = c0_ - 1;    // lf0
            val[2] = c1_ && (p1_ > 0);   srcC[2] = c1_c - RR;  // up1
            uint32_t* baseH = smu + OFF_T + buf_ * (6 * TILE_W);
#pragma unroll
            for (int f0 = 0; f0 < 1536; f0 += 256) {
                const int f = f0 + t;
                const int tl  = f >> 9;          // tile 0..2
                const int row = (f >> 4) & 31;   // batch row
                const int ch  = f & 15;          // 16B chunk (4 u32)
                uint32_t* dh = baseH + tl * TILE_W + row * PAD_T + ch * 4;
                uint32_t* dm = dh + 3 * TILE_W;
                if (val[tl]) {
                    size_t off = (srcC[tl] * Bz + row) * 64 + ch * 4;
                    CPA16(smem_u32(dh), g_hph + off);
                    CPA16(smem_u32(dm), g_hpm + off);
                } else {
                    *(uint4*)dh = make_uint4(0u, 0u, 0u, 0u);
                    *(uint4*)dm = make_uint4(0u, 0u, 0u, 0u);
                }
            }
        };

        int buf = 0;
        bool havePrefetch = false;

        for (int pi = j; pi < npairs; pi += 9) {
            const int q0 = qlo + 2 * pi;
            const int q1 = q0 + 1;
            const bool c1ok = (q1 <= qhi);
            const int p1 = s - q1;
            const size_t cell0 = dBase + (size_t)(s - q0) * RR + q0;
            const size_t cell1 = dBase + (size_t)p1 * RR + q1;

            if (!havePrefetch) { stageA(pi, buf); CPC(); }
            CPW0();
            __syncthreads();

            // prefetch next task on this diagonal into the other buffer
            const bool nxt = (pi + 9 < npairs);
            if (nxt) { stageA(pi + 9, buf ^ 1); CPC(); }

            uint32_t* bufBase = smu + OFF_T + buf * (6 * TILE_W);

            // ---- hoisted epilogue inputs: gx (global) + hu/hl (smem->regs) ----
            const bool doepi = !(mp == 1 && !c1ok);
            const size_t cellE = mp ? cell1 : cell0;
            const int kbase = kq * 32 + ng * 8 + 2 * ci;
            const int kpE = kbase >> 1;
            float2 grv[2][2], gzv[2][2], gnv[2][2];
            uint32_t huHr[2][2], huMr[2][2], hlHr[2][2], hlMr[2][2];
            {
                const uint32_t* huT = bufBase + (mp ? 2 : 0) * TILE_W;  // up
                const uint32_t* hlT = bufBase + (mp ? 0 : 1) * TILE_W;  // left
                if (doepi) {
#pragma unroll
                    for (int mt = 0; mt < 2; mt++) {
#pragma unroll
                        for (int half = 0; half < 2; half++) {
                            const int b = mt * 16 + half * 8 + gi;
                            const float* gxc = g_gx + (cellE * Bz + b) * Gg;
                            grv[mt][half] = __ldcg((const float2*)(gxc + kbase));
                            gzv[mt][half] = __ldcg((const float2*)(gxc + 128 + kbase));
                            gnv[mt][half] = __ldcg((const float2*)(gxc + 256 + kbase));
                            huHr[mt][half] = huT[b * PAD_T + kpE];
                            huMr[mt][half] = huT[b * PAD_T + kpE + 3 * TILE_W];
                            hlHr[mt][half] = hlT[b * PAD_T + kpE];
                            hlMr[mt][half] = hlT[b * PAD_T + kpE + 3 * TILE_W];
                        }
                    }
                }
            }

            // ---- bf16x3 MMA mainloop over K=256 (2 halves x 8 k8) ----
            float acc[2][3][4];
#pragma unroll
            for (int mt = 0; mt < 2; mt++)
#pragma unroll
                for (int g = 0; g < 3; g++)
#pragma unroll
                    for (int v = 0; v < 4; v++) acc[mt][g][v] = 0.f;

            const int cb0 = ng * 8 + gi;
            // warp tile selection: half0 = up (cell0->T0, cell1->T2);
            //                      half1 = left (cell0->T1, cell1->T0)
            const uint32_t* AhT[2] = {
                bufBase + (mp ? 2 : 0) * TILE_W,
                bufBase + (mp ? 0 : 1) * TILE_W };

#pragma unroll
            for (int half = 0; half < 2; half++) {
                const uint32_t* Aht = AhT[half];
                const uint32_t* Amt = Aht + 3 * TILE_W;
                // per-lane ldmatrix base addresses (bytes), mt 0/1, hi/mid
                unsigned adrH0 = smem_u32(Aht + ldm_row * PAD_T + ldm_koff);
                unsigned adrH1 = smem_u32(Aht + (16 + ldm_row) * PAD_T + ldm_koff);
                unsigned adrM0 = smem_u32(Amt + ldm_row * PAD_T + ldm_koff);
                unsigned adrM1 = smem_u32(Amt + (16 + ldm_row) * PAD_T + ldm_koff);
#pragma unroll 4
                for (int k8 = 0; k8 < 8; k8++) {
                    const int kpl = k8 * 8;              // kp within tile
                    const int kpw = half * 64 + kpl;     // W row
                    unsigned bh[3][2], bm[3][2];
#pragma unroll
                    for (int g = 0; g < 3; g++) {
                        const int c = g * 32 + cb0;
                        bh[g][0] = Wph_s[(kpw + ci) * PAD_W + c];
                        bh[g][1] = Wph_s[(kpw + ci + 4) * PAD_W + c];
                        bm[g][0] = Wpm_s[(kpw + ci) * PAD_W + c];
                        bm[g][1] = Wpm_s[(kpw + ci + 4) * PAD_W + c];
                    }
#pragma unroll
                    for (int mt = 0; mt < 2; mt++) {
                        unsigned ah0, ah1, ah2, ah3, am0, am1, am2, am3;
                        const unsigned ah_adr = (mt ? adrH1 : adrH0) + kpl * 4;
                        const unsigned am_adr = (mt ? adrM1 : adrM0) + kpl * 4;
                        LDSM4(ah0, ah1, ah2, ah3, ah_adr);
                        LDSM4(am0, am1, am2, am3, am_adr);
#pragma unroll
                        for (int g = 0; g < 3; g++) {
                            MMA_BF16(acc[mt][g], ah0, ah1, ah2, ah3, bh[g][0], bh[g][1]);
                            MMA_BF16(acc[mt][g], am0, am1, am2, am3, bh[g][0], bh[g][1]);
                            MMA_BF16(acc[mt][g], ah0, ah1, ah2, ah3, bm[g][0], bm[g][1]);
                        }
                    }
                }
            }

            // ---- GRU epilogue: pure register + global store ----
            if (doepi) {
#pragma unroll
                for (int mt = 0; mt < 2; mt++) {
#pragma unroll
                    for (int half = 0; half < 2; half++) {
                        const int b = mt * 16 + half * 8 + gi;
                        float2 gr = grv[mt][half];
                        float2 gz = gzv[mt][half];
                        float2 gn = gnv[mt][half];
                        float hu0 = bf_lo(huHr[mt][half]) + bf_lo(huMr[mt][half]);
                        float hu1 = bf_hi(huHr[mt][half]) + bf_hi(huMr[mt][half]);
                        float hl0 = bf_lo(hlHr[mt][half]) + bf_lo(hlMr[mt][half]);
                        float hl1 = bf_hi(hlHr[mt][half]) + bf_hi(hlMr[mt][half]);
                        float r0 = sigf(acc[mt][0][half * 2 + 0] + gr.x);
                        float r1 = sigf(acc[mt][0][half * 2 + 1] + gr.y);
                        float z0 = sigf(acc[mt][1][half * 2 + 0] + gz.x);
                        float z1 = sigf(acc[mt][1][half * 2 + 1] + gz.y);
                        float n0 = tanhf_fast(gn.x + r0 * acc[mt][2][half * 2 + 0]);
                        float n1 = tanhf_fast(gn.y + r1 * acc[mt][2][half * 2 + 1]);
                        float h0 = (1.f - z0) * n0 + z0 * 0.5f * (hu0 + hl0);
                        float h1 = (1.f - z1) * n1 + z1 * 0.5f * (hu1 + hl1);
                        uint32_t vh, vm;
                        split2(h0, h1, vh, vm);
                        size_t off = (cellE * Bz + b) * 64 + kpE;
                        g_hph[off] = vh;
                        g_hpm[off] = vm;
                    }
                }
            }
            // no trailing __syncthreads: buf smem reads all happened above;
            // the next iteration's CPW0+__syncthreads orders them against the
            // next prefetch write into this buffer.
            buf ^= 1;
            havePrefetch = nxt;
        }

        grid_barrier_d(d, s + 1);
    }
}

// ---------------------------------------------------------------------------
// Post-scan scatter (unchanged from R12 WIN).
__global__ void __launch_bounds__(256) scatter_kernel(float* __restrict__ out) {
    __shared__ float sm[32][129];
    const int bx = blockIdx.x;
    const int b  = blockIdx.y;
    const int d  = blockIdx.z;
    const int p  = bx >> 1;
    const int qt = bx & 1;
    const int qb = qt * 32;
    const int nq = qt ? 31 : 32;
    const int t  = threadIdx.x;

    for (int idx = t; idx < nq * 64; idx += 256) {
        const int qi = idx >> 6;
        const int kp = idx & 63;
        const size_t cell = (size_t)d * CELLS + (size_t)p * RR + (qb + qi);
        const size_t off = (cell * Bz + b) * 64 + kp;
        uint32_t vh = g_hph[off];
        uint32_t vm = g_hpm[off];
        sm[qi][2 * kp]     = bf_lo(vh) + bf_lo(vm);
        sm[qi][2 * kp + 1] = bf_hi(vh) + bf_hi(vm);
    }
    __syncthreads();

    const int oi = (d & 1) ? (63 - p) : p;
    for (int idx = t; idx < 32 * 128; idx += 256) {
        const int k  = idx >> 5;
        const int qi = idx & 31;
        if (qi < nq) {
            const int q  = qb + qi;
            const int oj = (d & 2) ? (63 - q) : q;
            out[((size_t)(b * 128 + k) * 4 + d) * 4096 + (size_t)oi * 64 + oj]
                = sm[qi][k];
        }
    }
}

// ---------------------------------------------------------------------------
extern "C" void kernel_launch(void* const* d_in, const int* in_sizes, int n_in,
                              void* d_out, int out_size) {
    const float* x    = (const float*)d_in[0];
    const float* Wx   = (const float*)d_in[1];
    const float* Wh   = (const float*)d_in[2];
    const float* Wh2  = (const float*)d_in[3];
    const float* bias = (const float*)d_in[4];
    float* out = (float*)d_out;

    cudaFuncSetAttribute(gx_mma_kernel,
                         cudaFuncAttributeMaxDynamicSharedMemorySize, GXM_SMEM);
    cudaFuncSetAttribute(scan_persist_kernel,
                         cudaFuncAttributeMaxDynamicSharedMemorySize, SCAN_SMEM);

    // 1) independent prep
    {
        dim3 grid(32, 4);
        border_fill_kernel<<<grid, 256>>>(out);
    }
    wsplit_kernel<<<768, 256>>>(Wh, Wh2);
    wxsplit_kernel<<<192, 256>>>(Wx);
    xsplit_kernel<<<4096, 256>>>(x);
    reset_kernel<<<1, 1>>>();

    // 2) gx via bf16x3 mma
    {
        dim3 grid(32, 63, 4);
        gx_mma_kernel<<<grid, 256, GXM_SMEM>>>(bias);
    }

    // 3) persistent bf16x3 wavefront scan (ldmatrix + prefetch + hoisted epi)
    scan_persist_kernel<<<NCTAS, 256, SCAN_SMEM>>>();

    // 4) coalesced transpose of h into the output layout
    {
        dim3 grid(126, 32, 4);
        scatter_kernel<<<grid, 256>>>(out);
    }
}